// round 13
// baseline (speedup 1.0000x reference)
#include <cuda_runtime.h>
#include <cuda_bf16.h>
#include <cstdint>

// Problem constants
#define NT   1024      // tokens = B*S
#define DDIM 768       // activation dim
#define FDIM 8192      // dict size
#define KTOP 64        // topk
#define CAND 96        // refinement candidates (margin 32 over KTOP)
#define CONN 128       // connections per downstream feature
#define NEDGE (FDIM*CONN)
#define BUCKET 256     // fixed per-f_up reverse-edge bucket (mean 128, 11 sigma safe)

// ---------------- device scratch (static globals; no cudaMalloc allowed) ----
__device__ float g_post[(size_t)NT * FDIM];       // upstream pre-topk approx (relu'd)
__device__ float g_dotD[(size_t)NT * FDIM];       // downstream raw dot approx
__device__ float g_xm[NT * DDIM];                 // (x_up - b_dec_up) fp32
__device__ float g_WtU[(size_t)FDIM * DDIM];      // W_dec_up^T   [F,D] fp32 (exact)
__device__ float g_WtD[(size_t)FDIM * DDIM];      // W_dec_down^T [F,D] fp32
__device__ __align__(16) __nv_bfloat16 g_WtUh[(size_t)FDIM * DDIM]; // bf16 (sddmm)
__device__ float g_cup[FDIM];                     // W_enc_down @ b_dec_up
__device__ float g_cdn[FDIM];                     // W_enc_down @ b_dec_down
__device__ int   g_tki_up[NT * KTOP];
__device__ float g_tkv_up[NT * KTOP];
__device__ int   g_tki_dn[NT * KTOP];
__device__ float g_tkv_dn[NT * KTOP];
__device__ int   g_cand_up[NT * CAND];
__device__ int   g_cand_dn[NT * CAND];
__device__ float g_candv_dn[NT * CAND];           // approx values at dn candidates
__device__ float g_eval[NEDGE];                   // approx masked virtual values (dup->0)
__device__ unsigned g_dupw[FDIM * 4];             // per-edge dup bitmask (CONN bits/f)
__device__ int   g_pos[FDIM];                     // bucket cursors (== final counts)
__device__ int2  g_rev[(size_t)FDIM * BUCKET];    // packed {f_down, eval bits}

// bf16 operands for tensor-core candidate GEMMs (selection-grade)
__device__ __align__(16) __nv_bfloat16 g_xhi[NT * DDIM];   // (x_up - b_dec_up)
__device__ __align__(16) __nv_bfloat16 g_0hi[NT * DDIM];   // initial_acts
__device__ __align__(16) __nv_bfloat16 g_Uhi[(size_t)FDIM * DDIM];  // W_enc_up
__device__ __align__(16) __nv_bfloat16 g_Dhi[(size_t)FDIM * DDIM];  // W_enc_down

// ======================= low-level helpers ==================================
__device__ __forceinline__ uint32_t s2u(const void* p) {
    uint32_t a;
    asm("{ .reg .u64 t; cvta.to.shared.u64 t, %1; cvt.u32.u64 %0, t; }"
        : "=r"(a) : "l"(p));
    return a;
}
__device__ __forceinline__ void cp16(uint32_t d, const void* s) {
    asm volatile("cp.async.cg.shared.global [%0], [%1], 16;"
                 :: "r"(d), "l"(s) : "memory");
}
#define CP_COMMIT() asm volatile("cp.async.commit_group;" ::: "memory")
#define CP_WAIT(n)  asm volatile("cp.async.wait_group %0;" :: "n"(n) : "memory")

#define LDSM4(r, a) \
    asm volatile("ldmatrix.sync.aligned.m8n8.x4.shared.b16 {%0,%1,%2,%3}, [%4];" \
        : "=r"((r)[0]), "=r"((r)[1]), "=r"((r)[2]), "=r"((r)[3]) : "r"(a))

#define MMA16816(d, a, b0, b1) \
    asm volatile("mma.sync.aligned.m16n8k16.row.col.f32.bf16.bf16.f32 " \
        "{%0,%1,%2,%3},{%4,%5,%6,%7},{%8,%9},{%0,%1,%2,%3};" \
        : "+f"((d)[0]), "+f"((d)[1]), "+f"((d)[2]), "+f"((d)[3]) \
        : "r"((a)[0]), "r"((a)[1]), "r"((a)[2]), "r"((a)[3]), "r"(b0), "r"(b1))

__device__ __forceinline__ unsigned fkey(float f) {
    unsigned u = __float_as_uint(f);
    return (u & 0x80000000u) ? ~u : (u | 0x80000000u);
}

// ---------------- prep / bf16 convert kernels --------------------------------
__global__ void split_xm_kernel(const float* __restrict__ xu,
                                const float* __restrict__ bdU) {
    int i = blockIdx.x * 256 + threadIdx.x;   // float4 index
    if (i >= NT * DDIM / 4) return;
    float4 v = ((const float4*)xu)[i];
    int col = (4 * i) % DDIM;
    v.x -= bdU[col]; v.y -= bdU[col + 1]; v.z -= bdU[col + 2]; v.w -= bdU[col + 3];
    ((float4*)g_xm)[i] = v;
    __nv_bfloat162* H = (__nv_bfloat162*)g_xhi;
    H[2 * i]     = __halves2bfloat162(__float2bfloat16(v.x), __float2bfloat16(v.y));
    H[2 * i + 1] = __halves2bfloat162(__float2bfloat16(v.z), __float2bfloat16(v.w));
}

// which: 0 -> x0 -> g_0hi, 1 -> WeU -> g_Uhi, 2 -> WeD -> g_Dhi (device-resolved)
__global__ void tobf16_kernel(const float* __restrict__ src, int which, int n4) {
    int i = blockIdx.x * 256 + threadIdx.x;
    if (i >= n4) return;
    __nv_bfloat16* hi = which == 0 ? g_0hi : (which == 1 ? g_Uhi : g_Dhi);
    float4 v = ((const float4*)src)[i];
    __nv_bfloat162* H = (__nv_bfloat162*)hi;
    H[2 * i]     = __halves2bfloat162(__float2bfloat16(v.x), __float2bfloat16(v.y));
    H[2 * i + 1] = __halves2bfloat162(__float2bfloat16(v.z), __float2bfloat16(v.w));
}

// ---------------- transpose W_dec_* [D,F] -> [F,D] (+bf16 WtU, zero g_pos) -
__global__ void transpose_kernel(const float* __restrict__ WdU,
                                 const float* __restrict__ WdD) {
    __shared__ float tile[32][33];
    const float* W = blockIdx.z ? WdD : WdU;
    float* Wt = blockIdx.z ? g_WtD : g_WtU;
    int c0 = blockIdx.x * 32, r0 = blockIdx.y * 32;
    int tx = threadIdx.x, ty = threadIdx.y;
    if (blockIdx.y == 0 && blockIdx.z == 0) {
        int idx = blockIdx.x * 256 + ty * 32 + tx;
        if (idx < FDIM) g_pos[idx] = 0;
    }
#pragma unroll
    for (int i = 0; i < 32; i += 8)
        tile[ty + i][tx] = W[(size_t)(r0 + ty + i) * FDIM + c0 + tx];
    __syncthreads();
#pragma unroll
    for (int i = 0; i < 32; i += 8) {
        float v = tile[tx][ty + i];
        size_t idx = (size_t)(c0 + ty + i) * DDIM + r0 + tx;
        Wt[idx] = v;
        if (blockIdx.z == 0) g_WtUh[idx] = __float2bfloat16(v);
    }
}

// ---------------- c_up/c_dn = W_enc_down @ b_dec_{up,down} -----------------
__global__ __launch_bounds__(256) void biasdot_kernel(
    const float* __restrict__ WeD, const float* __restrict__ bdU,
    const float* __restrict__ bdD) {
    int lane = threadIdx.x & 31, warp = threadIdx.x >> 5;
    int f = blockIdx.x * 8 + warp;
    const float4* w4 = (const float4*)(WeD + (size_t)f * DDIM);
    const float4* u4 = (const float4*)bdU;
    const float4* v4 = (const float4*)bdD;
    float su = 0.f, sd = 0.f;
    for (int q = lane; q < DDIM / 4; q += 32) {
        float4 a = w4[q], u = u4[q], v = v4[q];
        su += a.x * u.x + a.y * u.y + a.z * u.z + a.w * u.w;
        sd += a.x * v.x + a.y * v.y + a.z * v.z + a.w * v.w;
    }
#pragma unroll
    for (int o = 16; o; o >>= 1) {
        su += __shfl_xor_sync(0xffffffffu, su, o);
        sd += __shfl_xor_sync(0xffffffffu, sd, o);
    }
    if (lane == 0) { g_cup[f] = su; g_cdn[f] = sd; }
}

// =================== bf16 mma.sync GEMM: C = A @ B^T (candidate-grade) ======
#define BK 32
#define STAGE_BYTES 16384
#define GEMM_SMEM (3 * STAGE_BYTES)
#define NITER (DDIM / BK)

__global__ __launch_bounds__(256, 1) void gemm_mma(const float* __restrict__ beU) {
    extern __shared__ char smem[];
    const uint32_t sb = s2u(smem);
    const int tid = threadIdx.x;
    const int z = blockIdx.z;
    const int m0 = blockIdx.y << 7, n0 = blockIdx.x << 7;
    const __nv_bfloat16* Ahp = z ? g_0hi : g_xhi;
    const __nv_bfloat16* Bhp = z ? g_Dhi : g_Uhi;
    float* C = z ? g_dotD : g_post;

    const int lane = tid & 31, w = tid >> 5;
    const int wm = w >> 2, wn = w & 3;

    const int rowA = wm * 64 + (lane & 15);
    const int cA = lane >> 4;
    const int sA_ = (rowA >> 1) & 3;
    const int rowB = wn * 32 + ((lane >> 4) << 3) + (lane & 7);
    const int cB = (lane >> 3) & 1;
    const int sB_ = (rowB >> 1) & 3;

    float acc[4][4][4];
#pragma unroll
    for (int a = 0; a < 4; a++)
#pragma unroll
        for (int b = 0; b < 4; b++)
#pragma unroll
            for (int c = 0; c < 4; c++) acc[a][b][c] = 0.f;

    auto load_stage = [&](int it) {
        const int kk = it * BK;
        const uint32_t sbase = sb + (it % 3) * STAGE_BYTES;
#pragma unroll
        for (int i = 0; i < 2; i++) {
            int id = tid + (i << 8);
            int row = id >> 2, c = id & 3;
            const __nv_bfloat16* src = Ahp + (size_t)(m0 + row) * DDIM + kk + (c << 3);
            uint32_t dst = sbase + (row << 6) + ((c ^ ((row >> 1) & 3)) << 4);
            cp16(dst, src);
        }
#pragma unroll
        for (int i = 0; i < 2; i++) {
            int id = tid + (i << 8);
            int row = id >> 2, c = id & 3;
            const __nv_bfloat16* src = Bhp + (size_t)(n0 + row) * DDIM + kk + (c << 3);
            uint32_t dst = sbase + 8192 + (row << 6) + ((c ^ ((row >> 1) & 3)) << 4);
            cp16(dst, src);
        }
        CP_COMMIT();
    };

    load_stage(0);
    load_stage(1);

    for (int it = 0; it < NITER; it++) {
        if (it + 1 < NITER) { CP_WAIT(1); } else { CP_WAIT(0); }
        __syncthreads();

        const uint32_t sbase = sb + (it % 3) * STAGE_BYTES;
#pragma unroll
        for (int ks = 0; ks < 2; ks++) {
            uint32_t ah[4][4], bh[2][4];
            const int ca = ((ks << 1) + cA);
            const int cb = ((ks << 1) + cB);
#pragma unroll
            for (int mi = 0; mi < 4; mi++)
                LDSM4(ah[mi], sbase + ((rowA + (mi << 4)) << 6) + ((ca ^ sA_) << 4));
#pragma unroll
            for (int jb = 0; jb < 2; jb++)
                LDSM4(bh[jb], sbase + 8192 + ((rowB + (jb << 4)) << 6) +
                              ((cb ^ sB_) << 4));
#pragma unroll
            for (int mi = 0; mi < 4; mi++) {
#pragma unroll
                for (int nj = 0; nj < 4; nj++) {
                    const int jb = nj >> 1, o = (nj & 1) << 1;
                    MMA16816(acc[mi][nj], ah[mi], bh[jb][o], bh[jb][o + 1]);
                }
            }
        }
        __syncthreads();
        if (it + 2 < NITER) load_stage(it + 2);
    }

    const int g = lane >> 2, t4 = lane & 3;
#pragma unroll
    for (int mi = 0; mi < 4; mi++) {
#pragma unroll
        for (int nj = 0; nj < 4; nj++) {
            int row = m0 + wm * 64 + (mi << 4) + g;
            int col = n0 + wn * 32 + (nj << 3) + (t4 << 1);
            float v0 = acc[mi][nj][0], v1 = acc[mi][nj][1];
            float v2 = acc[mi][nj][2], v3 = acc[mi][nj][3];
            if (z == 0) {
                float b0 = __ldg(beU + col), b1 = __ldg(beU + col + 1);
                v0 = fmaxf(v0 + b0, 0.f); v1 = fmaxf(v1 + b1, 0.f);
                v2 = fmaxf(v2 + b0, 0.f); v3 = fmaxf(v3 + b1, 0.f);
            }
            *(float2*)(C + (size_t)row * FDIM + col) = make_float2(v0, v1);
            *(float2*)(C + (size_t)(row + 8) * FDIM + col) = make_float2(v2, v3);
        }
    }
}

// ---------------- upstream candidates: register-resident radix select ------
__global__ __launch_bounds__(256) void cand_up_kernel() {
    int n = blockIdx.x, t = threadIdx.x;
    __shared__ int hist[256];
    __shared__ unsigned s_pref;
    __shared__ int s_rem, s_cnt;

    unsigned key[32];
    const float4* p = (const float4*)(g_post + (size_t)n * FDIM);
#pragma unroll
    for (int j = 0; j < 8; j++) {
        float4 x = p[t + 256 * j];
        key[4 * j + 0] = fkey(x.x); key[4 * j + 1] = fkey(x.y);
        key[4 * j + 2] = fkey(x.z); key[4 * j + 3] = fkey(x.w);
    }
    if (t == 0) { s_pref = 0u; s_rem = CAND; s_cnt = 0; }
    __syncthreads();

    unsigned hmask = 0u;
    for (int pass = 0; pass < 4; pass++) {
        int sh = 24 - 8 * pass;
        hist[t] = 0;
        __syncthreads();
        unsigned pref = s_pref;
#pragma unroll
        for (int e = 0; e < 32; e++)
            if ((key[e] & hmask) == pref) atomicAdd(&hist[(key[e] >> sh) & 255], 1);
        __syncthreads();
        if (t == 0) {
            int rem = s_rem, c = 0, b = 255;
            for (; b >= 0; b--) { int h = hist[b]; if (c + h >= rem) break; c += h; }
            s_pref = pref | ((unsigned)b << sh);
            s_rem = rem - c;
        }
        hmask |= (0xFFu << sh);
        __syncthreads();
    }
    unsigned T = s_pref;
#pragma unroll
    for (int e = 0; e < 32; e++) {
        if (key[e] > T) {
            int q = atomicAdd(&s_cnt, 1);
            g_cand_up[n * CAND + q] = 4 * (t + 256 * (e >> 2)) + (e & 3);
        }
    }
    __syncthreads();
#pragma unroll
    for (int e = 0; e < 32; e++) {
        if (key[e] == T) {
            int q = atomicAdd(&s_cnt, 1);
            if (q < CAND) g_cand_up[n * CAND + q] = 4 * (t + 256 * (e >> 2)) + (e & 3);
        }
    }
}

// ---------------- refine: exact fp32 scores for candidates, exact top-K ----
// which=0: val = relu(g_xm[n]·WeU[f] + beU[f])
// which=1: val = candv + (x0·WeD[f] - dotD + corr) / ln, where
//   corr = sum over non-dup conn edges (f, j) with j in topk_up of
//          fv_j * (WeD[f]·WtU[j]_exact - g_eval[f,e])
__global__ __launch_bounds__(256) void refine_kernel(
    int which, const float* __restrict__ x0,
    const float* __restrict__ WeU, const float* __restrict__ WeD,
    const float* __restrict__ beU, const float* __restrict__ ln,
    const int* __restrict__ conn) {
    int n = blockIdx.x, t = threadIdx.x;
    int lane = t & 31, w = t >> 5;
    __shared__ float sx[DDIM];
    __shared__ float val8k[FDIM];     // topk_up value map (which==1 only)
    __shared__ float sval[128];
    __shared__ int sidx[128];

    const float* xsrc = which ? (x0 + (size_t)n * DDIM) : (g_xm + (size_t)n * DDIM);
    for (int i = t; i < DDIM; i += 256) sx[i] = xsrc[i];
    if (t >= CAND && t < 128) { sval[t] = -1e30f; sidx[t] = 0; }
    if (which) {
        for (int i = t; i < FDIM; i += 256) val8k[i] = 0.f;
    }
    __syncthreads();
    if (which && t < KTOP)
        val8k[g_tki_up[n * KTOP + t]] = g_tkv_up[n * KTOP + t];
    __syncthreads();

    const int* cand = which ? g_cand_dn : g_cand_up;
    const float* W = which ? WeD : WeU;
    const float inv = which ? (1.f / ln[n]) : 0.f;
    const float4* xr = (const float4*)sx;
    for (int c = w; c < CAND; c += 8) {
        int f = cand[n * CAND + c];
        const float4* wr = (const float4*)(W + (size_t)f * DDIM);
        float4 a[6];
        float s = 0.f;
#pragma unroll
        for (int q = 0; q < 6; q++) {
            a[q] = wr[lane + 32 * q];
            float4 b = xr[lane + 32 * q];
            s += a[q].x * b.x + a[q].y * b.y + a[q].z * b.z + a[q].w * b.w;
        }
#pragma unroll
        for (int o = 16; o; o >>= 1) s += __shfl_xor_sync(0xffffffffu, s, o);

        float v;
        if (which == 0) {
            v = fmaxf(s + beU[f], 0.f);
        } else {
            // exact correction of the pruned-accumulation term
            float corr = 0.f;
#pragma unroll
            for (int e4 = 0; e4 < 4; e4++) {
                int e = (e4 << 5) + lane;
                int j = conn[f * CONN + e];
                bool dupb = (g_dupw[f * 4 + e4] >> lane) & 1u;
                float fv = val8k[j];
                bool hit = (!dupb) && (fv != 0.f);
                unsigned hb = __ballot_sync(0xffffffffu, hit);
                while (hb) {
                    int src = __ffs(hb) - 1; hb &= hb - 1;
                    int jj = __shfl_sync(0xffffffffu, j, src);
                    const float4* bu = (const float4*)(g_WtU + (size_t)jj * DDIM);
                    float dd = 0.f;
#pragma unroll
                    for (int q = 0; q < 6; q++) {
                        float4 b = bu[lane + 32 * q];
                        dd += a[q].x * b.x + a[q].y * b.y + a[q].z * b.z + a[q].w * b.w;
                    }
#pragma unroll
                    for (int o = 16; o; o >>= 1) dd += __shfl_xor_sync(0xffffffffu, dd, o);
                    float ea = g_eval[f * CONN + (e4 << 5) + src];
                    corr += val8k[jj] * (dd - ea);
                }
            }
            v = g_candv_dn[n * CAND + c] +
                (s - g_dotD[(size_t)n * FDIM + f] + corr) * inv;
        }
        if (lane == 0) { sval[c] = v; sidx[c] = f; }
    }
    __syncthreads();

    // bitonic sort 128 descending
    for (int k = 2; k <= 128; k <<= 1) {
        for (int j = k >> 1; j > 0; j >>= 1) {
            if (t < 128) {
                int p = t ^ j;
                if (p > t) {
                    bool up = ((t & k) == 0);
                    float v0 = sval[t], v1 = sval[p];
                    bool sw = up ? (v0 < v1) : (v0 > v1);
                    if (sw) {
                        sval[t] = v1; sval[p] = v0;
                        int tmp = sidx[t]; sidx[t] = sidx[p]; sidx[p] = tmp;
                    }
                }
            }
            __syncthreads();
        }
    }

    if (t < KTOP) {
        if (which) { g_tki_dn[n * KTOP + t] = sidx[t]; g_tkv_dn[n * KTOP + t] = sval[t]; }
        else       { g_tki_up[n * KTOP + t] = sidx[t]; g_tkv_up[n * KTOP + t] = sval[t]; }
    }
}

// ---------------- SDDMM: approx masked virtual values (bf16 gather) --------
__global__ __launch_bounds__(256) void sddmm_kernel(
    const float* __restrict__ WeD, const int* __restrict__ conn) {
    int f = blockIdx.x;
    int t = threadIdx.x, lane = t & 31, warp = t >> 5;
    __shared__ int sconn[CONN];
    __shared__ unsigned bset[FDIM / 32];
    __shared__ unsigned char dup[CONN];
    if (t < CONN) sconn[t] = conn[f * CONN + t];
    bset[t] = 0u;
    __syncthreads();
    if (t < CONN) {
        int j = sconn[t];
        unsigned old = atomicOr(&bset[j >> 5], 1u << (j & 31));
        dup[t] = (unsigned char)((old >> (j & 31)) & 1u);
    }
    __syncthreads();
    if (warp < 4) {   // all 32 lanes have t < 128
        unsigned m = __ballot_sync(0xffffffffu, dup[t] != 0);
        if (lane == 0) g_dupw[f * 4 + warp] = m;
    }

    const float4* w4 = (const float4*)(WeD + (size_t)f * DDIM);
    float4 a[6];
#pragma unroll
    for (int q = 0; q < 6; q++) a[q] = w4[lane + 32 * q];

    for (int e = warp; e < CONN; e += 8) {
        int j = sconn[e];
        float v = 0.f;
        if (!dup[e]) {
            const uint2* b2 = (const uint2*)(g_WtUh + (size_t)j * DDIM);
#pragma unroll
            for (int q = 0; q < 6; q++) {
                uint2 raw = b2[lane + 32 * q];
                float2 b01 = __bfloat1622float2(*(const __nv_bfloat162*)&raw.x);
                float2 b23 = __bfloat1622float2(*(const __nv_bfloat162*)&raw.y);
                v += a[q].x * b01.x + a[q].y * b01.y + a[q].z * b23.x + a[q].w * b23.y;
            }
#pragma unroll
            for (int o = 16; o; o >>= 1) v += __shfl_xor_sync(0xffffffffu, v, o);
        }
        if (lane == 0) g_eval[f * CONN + e] = v;
    }
}

// ---------------- scatter edges into fixed-slot buckets --------------------
__global__ void scatter_kernel(const int* __restrict__ conn) {
    int e = blockIdx.x * 256 + threadIdx.x;
    int j = conn[e];
    int p = atomicAdd(&g_pos[j], 1);
    g_rev[(size_t)j * BUCKET + p] =
        make_int2(e >> 7, __float_as_int(g_eval[e]));
}

// ---------------- fused: accum + finalize + downstream candidate select ----
__global__ __launch_bounds__(256) void accum_cand_kernel(
    const float* __restrict__ beD, const float* __restrict__ ln) {
    int n = blockIdx.x, t = threadIdx.x;
    __shared__ float srow[FDIM];
    __shared__ int sidx[KTOP];
    __shared__ float sval[KTOP];
    __shared__ int hist[256];
    __shared__ unsigned s_pref;
    __shared__ int s_rem, s_cnt;

    for (int i = t; i < FDIM; i += 256) srow[i] = g_dotD[(size_t)n * FDIM + i];
    if (t < KTOP) { sidx[t] = g_tki_up[n * KTOP + t]; sval[t] = g_tkv_up[n * KTOP + t]; }
    if (t == 0) { s_pref = 0u; s_rem = CAND; s_cnt = 0; }
    __syncthreads();
    for (int k = 0; k < KTOP; k++) {
        float fv = sval[k];
        if (fv == 0.f) continue;
        int j = sidx[k];
        int cnt = g_pos[j];
        const int2* rv = g_rev + (size_t)j * BUCKET;
        for (int q = t; q < cnt; q += 256) {
            int2 r = rv[q];
            atomicAdd(&srow[r.x], fv * __int_as_float(r.y));
        }
    }
    __syncthreads();
    float inv = 1.f / ln[n];
    for (int i = t; i < FDIM; i += 256)
        srow[i] = (srow[i] + g_cup[i]) * inv + beD[i] - g_cdn[i];
    __syncthreads();

    unsigned hmask = 0u;
    for (int pass = 0; pass < 4; pass++) {
        int sh = 24 - 8 * pass;
        hist[t] = 0;
        __syncthreads();
        unsigned pref = s_pref;
        for (int i = t; i < FDIM; i += 256) {
            unsigned key = fkey(srow[i]);
            if ((key & hmask) == pref) atomicAdd(&hist[(key >> sh) & 255], 1);
        }
        __syncthreads();
        if (t == 0) {
            int rem = s_rem, c = 0, b = 255;
            for (; b >= 0; b--) { int h = hist[b]; if (c + h >= rem) break; c += h; }
            s_pref = pref | ((unsigned)b << sh);
            s_rem = rem - c;
        }
        hmask |= (0xFFu << sh);
        __syncthreads();
    }
    unsigned T = s_pref;
    for (int i = t; i < FDIM; i += 256) {
        if (fkey(srow[i]) > T) {
            int q = atomicAdd(&s_cnt, 1);
            g_cand_dn[n * CAND + q] = i;
            g_candv_dn[n * CAND + q] = srow[i];
        }
    }
    __syncthreads();
    for (int i = t; i < FDIM; i += 256) {
        if (fkey(srow[i]) == T) {
            int q = atomicAdd(&s_cnt, 1);
            if (q < CAND) {
                g_cand_dn[n * CAND + q] = i;
                g_candv_dn[n * CAND + q] = srow[i];
            }
        }
    }
}

// ---------------- sparse decode: out = bias + sum topk_v * Wt[idx] ---------
__global__ __launch_bounds__(256) void recon_kernel(
    int which, const float* __restrict__ bias, float* __restrict__ out) {
    int n = blockIdx.x, t = threadIdx.x;
    const float* Wt = which ? g_WtD : g_WtU;
    const int* ti = which ? g_tki_dn : g_tki_up;
    const float* tv = which ? g_tkv_dn : g_tkv_up;
    __shared__ int sidx[KTOP];
    __shared__ float sval[KTOP];
    if (t < KTOP) { sidx[t] = ti[n * KTOP + t]; sval[t] = tv[n * KTOP + t]; }
    __syncthreads();
    float a0 = bias[t], a1 = bias[t + 256], a2 = bias[t + 512];
    for (int k = 0; k < KTOP; k++) {
        const float* w = Wt + (size_t)sidx[k] * DDIM;
        float v = sval[k];
        a0 += v * w[t]; a1 += v * w[t + 256]; a2 += v * w[t + 512];
    }
    float* o = out + (size_t)n * DDIM;
    o[t] = a0; o[t + 256] = a1; o[t + 512] = a2;
}

// ---------------- launch: two-stream fork/join --------------------------------
extern "C" void kernel_launch(void* const* d_in, const int* in_sizes, int n_in,
                              void* d_out, int out_size) {
    (void)in_sizes; (void)n_in; (void)out_size;
    const float* x0  = (const float*)d_in[0];   // initial_acts
    const float* xu  = (const float*)d_in[1];   // x_up
    const float* ln  = (const float*)d_in[2];   // ln_scale [NT]
    const float* WeU = (const float*)d_in[3];   // W_enc_up [F,D]
    const float* beU = (const float*)d_in[4];   // b_enc_up [F]
    const float* WdU = (const float*)d_in[5];   // W_dec_up [D,F]
    const float* bdU = (const float*)d_in[6];   // b_dec_up [D]
    const float* WeD = (const float*)d_in[7];   // W_enc_down [F,D]
    const float* beD = (const float*)d_in[8];   // b_enc_down [F]
    const float* WdD = (const float*)d_in[9];   // W_dec_down [D,F]
    const float* bdD = (const float*)d_in[10];  // b_dec_down [D]
    const int*   conn = (const int*)d_in[11];   // [F,C]
    float* out = (float*)d_out;                 // [2,NT,DDIM]

    static cudaStream_t sB = nullptr;
    static cudaEvent_t evFork = nullptr, evT = nullptr, evJoin = nullptr;
    if (sB == nullptr) {
        int loPri, hiPri;
        cudaDeviceGetStreamPriorityRange(&loPri, &hiPri);
        cudaStreamCreateWithPriority(&sB, cudaStreamNonBlocking, hiPri);
        cudaEventCreateWithFlags(&evFork, cudaEventDisableTiming);
        cudaEventCreateWithFlags(&evT, cudaEventDisableTiming);
        cudaEventCreateWithFlags(&evJoin, cudaEventDisableTiming);
        cudaFuncSetAttribute(gemm_mma, cudaFuncAttributeMaxDynamicSharedMemorySize,
                             GEMM_SMEM);
    }

    // Fork stream B (transpose -> sddmm -> scatter -> biasdot); inputs-only deps.
    cudaEventRecord(evFork, 0);
    cudaStreamWaitEvent(sB, evFork, 0);
    transpose_kernel<<<dim3(FDIM / 32, DDIM / 32, 2), dim3(32, 8), 0, sB>>>(WdU, WdD);
    cudaEventRecord(evT, sB);   // WtU/WtD ready (needed by recon0 on main stream)
    sddmm_kernel<<<FDIM, 256, 0, sB>>>(WeD, conn);
    scatter_kernel<<<NEDGE / 256, 256, 0, sB>>>(conn);
    biasdot_kernel<<<FDIM / 8, 256, 0, sB>>>(WeD, bdU, bdD);
    cudaEventRecord(evJoin, sB);

    // Main stream: upstream spine.
    split_xm_kernel<<<(NT * DDIM / 4 + 255) / 256, 256>>>(xu, bdU);
    tobf16_kernel<<<(NT * DDIM / 4 + 255) / 256, 256>>>(x0, 0, NT * DDIM / 4);
    tobf16_kernel<<<(FDIM * DDIM / 4 + 255) / 256, 256>>>(WeU, 1, FDIM * DDIM / 4);
    tobf16_kernel<<<(FDIM * DDIM / 4 + 255) / 256, 256>>>(WeD, 2, FDIM * DDIM / 4);
    gemm_mma<<<dim3(FDIM / 128, NT / 128, 2), 256, GEMM_SMEM>>>(beU);
    cand_up_kernel<<<NT, 256>>>();
    refine_kernel<<<NT, 256>>>(0, x0, WeU, WeD, beU, ln, conn);
    cudaStreamWaitEvent(0, evT, 0);      // recon0 reads g_WtU (transpose output)
    recon_kernel<<<NT, 256>>>(0, bdU, out);

    // Join stream B, then downstream tail.
    cudaStreamWaitEvent(0, evJoin, 0);
    accum_cand_kernel<<<NT, 256>>>(beD, ln);
    refine_kernel<<<NT, 256>>>(1, x0, WeU, WeD, beU, ln, conn);
    recon_kernel<<<NT, 256>>>(1, bdD, out + (size_t)NT * DDIM);
}

// round 14
// speedup vs baseline: 1.0337x; 1.0337x over previous
#include <cuda_runtime.h>
#include <cuda_bf16.h>
#include <cstdint>

// Problem constants
#define NT   1024      // tokens = B*S
#define DDIM 768       // activation dim
#define FDIM 8192      // dict size
#define KTOP 64        // topk
#define CAND 96        // refinement candidates (margin 32 over KTOP)
#define CONN 128       // connections per downstream feature
#define NEDGE (FDIM*CONN)
#define BUCKET 256     // fixed per-f_up reverse-edge bucket (mean 128, 11 sigma safe)

// ---------------- device scratch (static globals; no cudaMalloc allowed) ----
__device__ float g_post[(size_t)NT * FDIM];       // upstream pre-topk approx (relu'd)
__device__ float g_dotD[(size_t)NT * FDIM];       // downstream raw dot approx
__device__ float g_xm[NT * DDIM];                 // (x_up - b_dec_up) fp32
__device__ float g_WtU[(size_t)FDIM * DDIM];      // W_dec_up^T   [F,D] fp32
__device__ float g_WtD[(size_t)FDIM * DDIM];      // W_dec_down^T [F,D] fp32
__device__ float g_cup[FDIM];                     // W_enc_down @ b_dec_up
__device__ float g_cdn[FDIM];                     // W_enc_down @ b_dec_down
__device__ int   g_tki_up[NT * KTOP];
__device__ float g_tkv_up[NT * KTOP];
__device__ int   g_tki_dn[NT * KTOP];
__device__ float g_tkv_dn[NT * KTOP];
__device__ int   g_cand_up[NT * CAND];
__device__ int   g_cand_dn[NT * CAND];
__device__ float g_candv_dn[NT * CAND];           // approx values at dn candidates
__device__ int   g_pos[FDIM];                     // bucket cursors (== final counts)
__device__ int2  g_rev[(size_t)FDIM * BUCKET];    // packed {f_down, eval bits}

// bf16 operands for tensor-core candidate GEMMs (selection-grade)
__device__ __align__(16) __nv_bfloat16 g_xhi[NT * DDIM];   // (x_up - b_dec_up)
__device__ __align__(16) __nv_bfloat16 g_0hi[NT * DDIM];   // initial_acts
__device__ __align__(16) __nv_bfloat16 g_Uhi[(size_t)FDIM * DDIM];  // W_enc_up
__device__ __align__(16) __nv_bfloat16 g_Dhi[(size_t)FDIM * DDIM];  // W_enc_down

// ======================= low-level helpers ==================================
__device__ __forceinline__ uint32_t s2u(const void* p) {
    uint32_t a;
    asm("{ .reg .u64 t; cvta.to.shared.u64 t, %1; cvt.u32.u64 %0, t; }"
        : "=r"(a) : "l"(p));
    return a;
}
__device__ __forceinline__ void cp16(uint32_t d, const void* s) {
    asm volatile("cp.async.cg.shared.global [%0], [%1], 16;"
                 :: "r"(d), "l"(s) : "memory");
}
#define CP_COMMIT() asm volatile("cp.async.commit_group;" ::: "memory")
#define CP_WAIT(n)  asm volatile("cp.async.wait_group %0;" :: "n"(n) : "memory")

#define LDSM4(r, a) \
    asm volatile("ldmatrix.sync.aligned.m8n8.x4.shared.b16 {%0,%1,%2,%3}, [%4];" \
        : "=r"((r)[0]), "=r"((r)[1]), "=r"((r)[2]), "=r"((r)[3]) : "r"(a))

#define MMA16816(d, a, b0, b1) \
    asm volatile("mma.sync.aligned.m16n8k16.row.col.f32.bf16.bf16.f32 " \
        "{%0,%1,%2,%3},{%4,%5,%6,%7},{%8,%9},{%0,%1,%2,%3};" \
        : "+f"((d)[0]), "+f"((d)[1]), "+f"((d)[2]), "+f"((d)[3]) \
        : "r"((a)[0]), "r"((a)[1]), "r"((a)[2]), "r"((a)[3]), "r"(b0), "r"(b1))

__device__ __forceinline__ unsigned fkey(float f) {
    unsigned u = __float_as_uint(f);
    return (u & 0x80000000u) ? ~u : (u | 0x80000000u);
}

// ---------------- prep / bf16 convert kernels --------------------------------
__global__ void split_xm_kernel(const float* __restrict__ xu,
                                const float* __restrict__ bdU) {
    int i = blockIdx.x * 256 + threadIdx.x;   // float4 index
    if (i >= NT * DDIM / 4) return;
    float4 v = ((const float4*)xu)[i];
    int col = (4 * i) % DDIM;
    v.x -= bdU[col]; v.y -= bdU[col + 1]; v.z -= bdU[col + 2]; v.w -= bdU[col + 3];
    ((float4*)g_xm)[i] = v;
    __nv_bfloat162* H = (__nv_bfloat162*)g_xhi;
    H[2 * i]     = __halves2bfloat162(__float2bfloat16(v.x), __float2bfloat16(v.y));
    H[2 * i + 1] = __halves2bfloat162(__float2bfloat16(v.z), __float2bfloat16(v.w));
}

// which: 0 -> x0 -> g_0hi, 1 -> WeU -> g_Uhi, 2 -> WeD -> g_Dhi (device-resolved)
__global__ void tobf16_kernel(const float* __restrict__ src, int which, int n4) {
    int i = blockIdx.x * 256 + threadIdx.x;
    if (i >= n4) return;
    __nv_bfloat16* hi = which == 0 ? g_0hi : (which == 1 ? g_Uhi : g_Dhi);
    float4 v = ((const float4*)src)[i];
    __nv_bfloat162* H = (__nv_bfloat162*)hi;
    H[2 * i]     = __halves2bfloat162(__float2bfloat16(v.x), __float2bfloat16(v.y));
    H[2 * i + 1] = __halves2bfloat162(__float2bfloat16(v.z), __float2bfloat16(v.w));
}

// ---------------- transpose W_dec [D,F] -> [F,D] ---------------------------
// which=0: WdU -> g_WtU (and zero g_pos, consumed by fused sddmm/scatter)
// which=1: WdD -> g_WtD
__global__ void transpose_kernel(const float* __restrict__ W, int which) {
    __shared__ float tile[32][33];
    float* Wt = which ? g_WtD : g_WtU;
    int c0 = blockIdx.x * 32, r0 = blockIdx.y * 32;
    int tx = threadIdx.x, ty = threadIdx.y;
    if (which == 0 && blockIdx.y == 0) {
        int idx = blockIdx.x * 256 + ty * 32 + tx;
        if (idx < FDIM) g_pos[idx] = 0;
    }
#pragma unroll
    for (int i = 0; i < 32; i += 8)
        tile[ty + i][tx] = W[(size_t)(r0 + ty + i) * FDIM + c0 + tx];
    __syncthreads();
#pragma unroll
    for (int i = 0; i < 32; i += 8)
        Wt[(size_t)(c0 + ty + i) * DDIM + r0 + tx] = tile[tx][ty + i];
}

// ---------------- c_up/c_dn = W_enc_down @ b_dec_{up,down} -----------------
__global__ __launch_bounds__(256) void biasdot_kernel(
    const float* __restrict__ WeD, const float* __restrict__ bdU,
    const float* __restrict__ bdD) {
    int lane = threadIdx.x & 31, warp = threadIdx.x >> 5;
    int f = blockIdx.x * 8 + warp;
    const float4* w4 = (const float4*)(WeD + (size_t)f * DDIM);
    const float4* u4 = (const float4*)bdU;
    const float4* v4 = (const float4*)bdD;
    float su = 0.f, sd = 0.f;
    for (int q = lane; q < DDIM / 4; q += 32) {
        float4 a = w4[q], u = u4[q], v = v4[q];
        su += a.x * u.x + a.y * u.y + a.z * u.z + a.w * u.w;
        sd += a.x * v.x + a.y * v.y + a.z * v.z + a.w * v.w;
    }
#pragma unroll
    for (int o = 16; o; o >>= 1) {
        su += __shfl_xor_sync(0xffffffffu, su, o);
        sd += __shfl_xor_sync(0xffffffffu, sd, o);
    }
    if (lane == 0) { g_cup[f] = su; g_cdn[f] = sd; }
}

// =================== bf16 mma.sync GEMM: C = A @ B^T (candidate-grade) ======
#define BK 32
#define STAGE_BYTES 16384
#define GEMM_SMEM (3 * STAGE_BYTES)
#define NITER (DDIM / BK)

__global__ __launch_bounds__(256, 1) void gemm_mma(const float* __restrict__ beU) {
    extern __shared__ char smem[];
    const uint32_t sb = s2u(smem);
    const int tid = threadIdx.x;
    const int z = blockIdx.z;
    const int m0 = blockIdx.y << 7, n0 = blockIdx.x << 7;
    const __nv_bfloat16* Ahp = z ? g_0hi : g_xhi;
    const __nv_bfloat16* Bhp = z ? g_Dhi : g_Uhi;
    float* C = z ? g_dotD : g_post;

    const int lane = tid & 31, w = tid >> 5;
    const int wm = w >> 2, wn = w & 3;

    const int rowA = wm * 64 + (lane & 15);
    const int cA = lane >> 4;
    const int sA_ = (rowA >> 1) & 3;
    const int rowB = wn * 32 + ((lane >> 4) << 3) + (lane & 7);
    const int cB = (lane >> 3) & 1;
    const int sB_ = (rowB >> 1) & 3;

    float acc[4][4][4];
#pragma unroll
    for (int a = 0; a < 4; a++)
#pragma unroll
        for (int b = 0; b < 4; b++)
#pragma unroll
            for (int c = 0; c < 4; c++) acc[a][b][c] = 0.f;

    auto load_stage = [&](int it) {
        const int kk = it * BK;
        const uint32_t sbase = sb + (it % 3) * STAGE_BYTES;
#pragma unroll
        for (int i = 0; i < 2; i++) {
            int id = tid + (i << 8);
            int row = id >> 2, c = id & 3;
            const __nv_bfloat16* src = Ahp + (size_t)(m0 + row) * DDIM + kk + (c << 3);
            uint32_t dst = sbase + (row << 6) + ((c ^ ((row >> 1) & 3)) << 4);
            cp16(dst, src);
        }
#pragma unroll
        for (int i = 0; i < 2; i++) {
            int id = tid + (i << 8);
            int row = id >> 2, c = id & 3;
            const __nv_bfloat16* src = Bhp + (size_t)(n0 + row) * DDIM + kk + (c << 3);
            uint32_t dst = sbase + 8192 + (row << 6) + ((c ^ ((row >> 1) & 3)) << 4);
            cp16(dst, src);
        }
        CP_COMMIT();
    };

    load_stage(0);
    load_stage(1);

    for (int it = 0; it < NITER; it++) {
        if (it + 1 < NITER) { CP_WAIT(1); } else { CP_WAIT(0); }
        __syncthreads();

        const uint32_t sbase = sb + (it % 3) * STAGE_BYTES;
#pragma unroll
        for (int ks = 0; ks < 2; ks++) {
            uint32_t ah[4][4], bh[2][4];
            const int ca = ((ks << 1) + cA);
            const int cb = ((ks << 1) + cB);
#pragma unroll
            for (int mi = 0; mi < 4; mi++)
                LDSM4(ah[mi], sbase + ((rowA + (mi << 4)) << 6) + ((ca ^ sA_) << 4));
#pragma unroll
            for (int jb = 0; jb < 2; jb++)
                LDSM4(bh[jb], sbase + 8192 + ((rowB + (jb << 4)) << 6) +
                              ((cb ^ sB_) << 4));
#pragma unroll
            for (int mi = 0; mi < 4; mi++) {
#pragma unroll
                for (int nj = 0; nj < 4; nj++) {
                    const int jb = nj >> 1, o = (nj & 1) << 1;
                    MMA16816(acc[mi][nj], ah[mi], bh[jb][o], bh[jb][o + 1]);
                }
            }
        }
        __syncthreads();
        if (it + 2 < NITER) load_stage(it + 2);
    }

    const int g = lane >> 2, t4 = lane & 3;
#pragma unroll
    for (int mi = 0; mi < 4; mi++) {
#pragma unroll
        for (int nj = 0; nj < 4; nj++) {
            int row = m0 + wm * 64 + (mi << 4) + g;
            int col = n0 + wn * 32 + (nj << 3) + (t4 << 1);
            float v0 = acc[mi][nj][0], v1 = acc[mi][nj][1];
            float v2 = acc[mi][nj][2], v3 = acc[mi][nj][3];
            if (z == 0) {
                float b0 = __ldg(beU + col), b1 = __ldg(beU + col + 1);
                v0 = fmaxf(v0 + b0, 0.f); v1 = fmaxf(v1 + b1, 0.f);
                v2 = fmaxf(v2 + b0, 0.f); v3 = fmaxf(v3 + b1, 0.f);
            }
            *(float2*)(C + (size_t)row * FDIM + col) = make_float2(v0, v1);
            *(float2*)(C + (size_t)(row + 8) * FDIM + col) = make_float2(v2, v3);
        }
    }
}

// ---------------- upstream candidates: register-resident radix select ------
__global__ __launch_bounds__(256) void cand_up_kernel() {
    int n = blockIdx.x, t = threadIdx.x;
    __shared__ int hist[256];
    __shared__ unsigned s_pref;
    __shared__ int s_rem, s_cnt;

    unsigned key[32];
    const float4* p = (const float4*)(g_post + (size_t)n * FDIM);
#pragma unroll
    for (int j = 0; j < 8; j++) {
        float4 x = p[t + 256 * j];
        key[4 * j + 0] = fkey(x.x); key[4 * j + 1] = fkey(x.y);
        key[4 * j + 2] = fkey(x.z); key[4 * j + 3] = fkey(x.w);
    }
    if (t == 0) { s_pref = 0u; s_rem = CAND; s_cnt = 0; }
    __syncthreads();

    unsigned hmask = 0u;
    for (int pass = 0; pass < 4; pass++) {
        int sh = 24 - 8 * pass;
        hist[t] = 0;
        __syncthreads();
        unsigned pref = s_pref;
#pragma unroll
        for (int e = 0; e < 32; e++)
            if ((key[e] & hmask) == pref) atomicAdd(&hist[(key[e] >> sh) & 255], 1);
        __syncthreads();
        if (t == 0) {
            int rem = s_rem, c = 0, b = 255;
            for (; b >= 0; b--) { int h = hist[b]; if (c + h >= rem) break; c += h; }
            s_pref = pref | ((unsigned)b << sh);
            s_rem = rem - c;
        }
        hmask |= (0xFFu << sh);
        __syncthreads();
    }
    unsigned T = s_pref;
#pragma unroll
    for (int e = 0; e < 32; e++) {
        if (key[e] > T) {
            int q = atomicAdd(&s_cnt, 1);
            g_cand_up[n * CAND + q] = 4 * (t + 256 * (e >> 2)) + (e & 3);
        }
    }
    __syncthreads();
#pragma unroll
    for (int e = 0; e < 32; e++) {
        if (key[e] == T) {
            int q = atomicAdd(&s_cnt, 1);
            if (q < CAND) g_cand_up[n * CAND + q] = 4 * (t + 256 * (e >> 2)) + (e & 3);
        }
    }
}

// ---------------- refine: exact fp32 scores for candidates, exact top-K ----
__global__ __launch_bounds__(256) void refine_kernel(
    int which, const float* __restrict__ x0,
    const float* __restrict__ WeU, const float* __restrict__ WeD,
    const float* __restrict__ beU, const float* __restrict__ ln) {
    int n = blockIdx.x, t = threadIdx.x;
    int lane = t & 31, w = t >> 5;
    __shared__ float sx[DDIM];
    __shared__ float sval[128];
    __shared__ int sidx[128];

    const float* xsrc = which ? (x0 + (size_t)n * DDIM) : (g_xm + (size_t)n * DDIM);
    for (int i = t; i < DDIM; i += 256) sx[i] = xsrc[i];
    if (t >= CAND && t < 128) { sval[t] = -1e30f; sidx[t] = 0; }
    __syncthreads();

    const int* cand = which ? g_cand_dn : g_cand_up;
    const float* W = which ? WeD : WeU;
    const float inv = which ? (1.f / ln[n]) : 0.f;
    for (int c = w; c < CAND; c += 8) {
        int f = cand[n * CAND + c];
        const float4* wr = (const float4*)(W + (size_t)f * DDIM);
        const float4* xr = (const float4*)sx;
        float s = 0.f;
#pragma unroll
        for (int q = lane; q < DDIM / 4; q += 32) {
            float4 a = wr[q], b = xr[q];
            s += a.x * b.x + a.y * b.y + a.z * b.z + a.w * b.w;
        }
#pragma unroll
        for (int o = 16; o; o >>= 1) s += __shfl_xor_sync(0xffffffffu, s, o);
        if (lane == 0) {
            float v;
            if (which == 0) {
                v = fmaxf(s + beU[f], 0.f);
            } else {
                v = g_candv_dn[n * CAND + c] +
                    (s - g_dotD[(size_t)n * FDIM + f]) * inv;
            }
            sval[c] = v; sidx[c] = f;
        }
    }
    __syncthreads();

    // bitonic sort 128 descending
    for (int k = 2; k <= 128; k <<= 1) {
        for (int j = k >> 1; j > 0; j >>= 1) {
            if (t < 128) {
                int p = t ^ j;
                if (p > t) {
                    bool up = ((t & k) == 0);
                    float v0 = sval[t], v1 = sval[p];
                    bool sw = up ? (v0 < v1) : (v0 > v1);
                    if (sw) {
                        sval[t] = v1; sval[p] = v0;
                        int tmp = sidx[t]; sidx[t] = sidx[p]; sidx[p] = tmp;
                    }
                }
            }
            __syncthreads();
        }
    }

    if (t < KTOP) {
        if (which) { g_tki_dn[n * KTOP + t] = sidx[t]; g_tkv_dn[n * KTOP + t] = sval[t]; }
        else       { g_tki_up[n * KTOP + t] = sidx[t]; g_tkv_up[n * KTOP + t] = sval[t]; }
    }
}

// ---------------- fused SDDMM + scatter: edge dots -> reverse buckets ------
// fp32 gather of g_WtU rows (exact); duplicates carry v=0; every edge written.
__global__ __launch_bounds__(256) void sddmm_scatter_kernel(
    const float* __restrict__ WeD, const int* __restrict__ conn) {
    int f = blockIdx.x;
    int t = threadIdx.x, lane = t & 31, warp = t >> 5;
    __shared__ int sconn[CONN];
    __shared__ unsigned bset[FDIM / 32];
    __shared__ unsigned char dup[CONN];
    if (t < CONN) sconn[t] = conn[f * CONN + t];
    bset[t] = 0u;
    __syncthreads();
    if (t < CONN) {
        int j = sconn[t];
        unsigned old = atomicOr(&bset[j >> 5], 1u << (j & 31));
        dup[t] = (unsigned char)((old >> (j & 31)) & 1u);
    }
    __syncthreads();

    const float4* w4 = (const float4*)(WeD + (size_t)f * DDIM);
    float4 a[6];
#pragma unroll
    for (int q = 0; q < 6; q++) a[q] = w4[lane + 32 * q];

    for (int e = warp; e < CONN; e += 8) {
        int j = sconn[e];
        float v = 0.f;
        if (!dup[e]) {
            const float4* b4 = (const float4*)(g_WtU + (size_t)j * DDIM);
#pragma unroll
            for (int q = 0; q < 6; q++) {
                float4 b = b4[lane + 32 * q];
                v += a[q].x * b.x + a[q].y * b.y + a[q].z * b.z + a[q].w * b.w;
            }
#pragma unroll
            for (int o = 16; o; o >>= 1) v += __shfl_xor_sync(0xffffffffu, v, o);
        }
        if (lane == 0) {
            int p = atomicAdd(&g_pos[j], 1);
            g_rev[(size_t)j * BUCKET + p] = make_int2(f, __float_as_int(v));
        }
    }
}

// ---------------- fused: accum + finalize + downstream candidate select ----
__global__ __launch_bounds__(256) void accum_cand_kernel(
    const float* __restrict__ beD, const float* __restrict__ ln) {
    int n = blockIdx.x, t = threadIdx.x;
    __shared__ float srow[FDIM];
    __shared__ int sidx[KTOP];
    __shared__ float sval[KTOP];
    __shared__ int hist[256];
    __shared__ unsigned s_pref;
    __shared__ int s_rem, s_cnt;

    for (int i = t; i < FDIM; i += 256) srow[i] = g_dotD[(size_t)n * FDIM + i];
    if (t < KTOP) { sidx[t] = g_tki_up[n * KTOP + t]; sval[t] = g_tkv_up[n * KTOP + t]; }
    if (t == 0) { s_pref = 0u; s_rem = CAND; s_cnt = 0; }
    __syncthreads();
    for (int k = 0; k < KTOP; k++) {
        float fv = sval[k];
        if (fv == 0.f) continue;
        int j = sidx[k];
        int cnt = g_pos[j];
        const int2* rv = g_rev + (size_t)j * BUCKET;
        for (int q = t; q < cnt; q += 256) {
            int2 r = rv[q];
            atomicAdd(&srow[r.x], fv * __int_as_float(r.y));
        }
    }
    __syncthreads();
    float inv = 1.f / ln[n];
    for (int i = t; i < FDIM; i += 256)
        srow[i] = (srow[i] + g_cup[i]) * inv + beD[i] - g_cdn[i];
    __syncthreads();

    unsigned hmask = 0u;
    for (int pass = 0; pass < 4; pass++) {
        int sh = 24 - 8 * pass;
        hist[t] = 0;
        __syncthreads();
        unsigned pref = s_pref;
        for (int i = t; i < FDIM; i += 256) {
            unsigned key = fkey(srow[i]);
            if ((key & hmask) == pref) atomicAdd(&hist[(key >> sh) & 255], 1);
        }
        __syncthreads();
        if (t == 0) {
            int rem = s_rem, c = 0, b = 255;
            for (; b >= 0; b--) { int h = hist[b]; if (c + h >= rem) break; c += h; }
            s_pref = pref | ((unsigned)b << sh);
            s_rem = rem - c;
        }
        hmask |= (0xFFu << sh);
        __syncthreads();
    }
    unsigned T = s_pref;
    for (int i = t; i < FDIM; i += 256) {
        if (fkey(srow[i]) > T) {
            int q = atomicAdd(&s_cnt, 1);
            g_cand_dn[n * CAND + q] = i;
            g_candv_dn[n * CAND + q] = srow[i];
        }
    }
    __syncthreads();
    for (int i = t; i < FDIM; i += 256) {
        if (fkey(srow[i]) == T) {
            int q = atomicAdd(&s_cnt, 1);
            if (q < CAND) {
                g_cand_dn[n * CAND + q] = i;
                g_candv_dn[n * CAND + q] = srow[i];
            }
        }
    }
}

// ---------------- sparse decode: out = bias + sum topk_v * Wt[idx] ---------
__global__ __launch_bounds__(256) void recon_kernel(
    int which, const float* __restrict__ bias, float* __restrict__ out) {
    int n = blockIdx.x, t = threadIdx.x;
    const float* Wt = which ? g_WtD : g_WtU;
    const int* ti = which ? g_tki_dn : g_tki_up;
    const float* tv = which ? g_tkv_dn : g_tkv_up;
    __shared__ int sidx[KTOP];
    __shared__ float sval[KTOP];
    if (t < KTOP) { sidx[t] = ti[n * KTOP + t]; sval[t] = tv[n * KTOP + t]; }
    __syncthreads();
    float a0 = bias[t], a1 = bias[t + 256], a2 = bias[t + 512];
    for (int k = 0; k < KTOP; k++) {
        const float* w = Wt + (size_t)sidx[k] * DDIM;
        float v = sval[k];
        a0 += v * w[t]; a1 += v * w[t + 256]; a2 += v * w[t + 512];
    }
    float* o = out + (size_t)n * DDIM;
    o[t] = a0; o[t + 256] = a1; o[t + 512] = a2;
}

// ---------------- launch: two-stream fork/join --------------------------------
extern "C" void kernel_launch(void* const* d_in, const int* in_sizes, int n_in,
                              void* d_out, int out_size) {
    (void)in_sizes; (void)n_in; (void)out_size;
    const float* x0  = (const float*)d_in[0];   // initial_acts
    const float* xu  = (const float*)d_in[1];   // x_up
    const float* ln  = (const float*)d_in[2];   // ln_scale [NT]
    const float* WeU = (const float*)d_in[3];   // W_enc_up [F,D]
    const float* beU = (const float*)d_in[4];   // b_enc_up [F]
    const float* WdU = (const float*)d_in[5];   // W_dec_up [D,F]
    const float* bdU = (const float*)d_in[6];   // b_dec_up [D]
    const float* WeD = (const float*)d_in[7];   // W_enc_down [F,D]
    const float* beD = (const float*)d_in[8];   // b_enc_down [F]
    const float* WdD = (const float*)d_in[9];   // W_dec_down [D,F]
    const float* bdD = (const float*)d_in[10];  // b_dec_down [D]
    const int*   conn = (const int*)d_in[11];   // [F,C]
    float* out = (float*)d_out;                 // [2,NT,DDIM]

    static cudaStream_t sB = nullptr;
    static cudaEvent_t evFork = nullptr, evT = nullptr, evJoin = nullptr;
    if (sB == nullptr) {
        int loPri, hiPri;
        cudaDeviceGetStreamPriorityRange(&loPri, &hiPri);
        cudaStreamCreateWithPriority(&sB, cudaStreamNonBlocking, hiPri);
        cudaEventCreateWithFlags(&evFork, cudaEventDisableTiming);
        cudaEventCreateWithFlags(&evT, cudaEventDisableTiming);
        cudaEventCreateWithFlags(&evJoin, cudaEventDisableTiming);
        cudaFuncSetAttribute(gemm_mma, cudaFuncAttributeMaxDynamicSharedMemorySize,
                             GEMM_SMEM);
    }

    // Fork stream B: WtU transpose -> fused sddmm+scatter. Minimal critical path.
    cudaEventRecord(evFork, 0);
    cudaStreamWaitEvent(sB, evFork, 0);
    transpose_kernel<<<dim3(FDIM / 32, DDIM / 32), dim3(32, 8), 0, sB>>>(WdU, 0);
    cudaEventRecord(evT, sB);   // g_WtU ready (needed by recon0 on main stream)
    sddmm_scatter_kernel<<<FDIM, 256, 0, sB>>>(WeD, conn);
    cudaEventRecord(evJoin, sB);

    // Main stream: upstream spine (+ biasdot & WtD transpose in slack).
    biasdot_kernel<<<FDIM / 8, 256>>>(WeD, bdU, bdD);
    transpose_kernel<<<dim3(FDIM / 32, DDIM / 32), dim3(32, 8)>>>(WdD, 1);
    split_xm_kernel<<<(NT * DDIM / 4 + 255) / 256, 256>>>(xu, bdU);
    tobf16_kernel<<<(NT * DDIM / 4 + 255) / 256, 256>>>(x0, 0, NT * DDIM / 4);
    tobf16_kernel<<<(FDIM * DDIM / 4 + 255) / 256, 256>>>(WeU, 1, FDIM * DDIM / 4);
    tobf16_kernel<<<(FDIM * DDIM / 4 + 255) / 256, 256>>>(WeD, 2, FDIM * DDIM / 4);
    gemm_mma<<<dim3(FDIM / 128, NT / 128, 2), 256, GEMM_SMEM>>>(beU);
    cand_up_kernel<<<NT, 256>>>();
    refine_kernel<<<NT, 256>>>(0, x0, WeU, WeD, beU, ln);
    cudaStreamWaitEvent(0, evT, 0);      // recon0 reads g_WtU
    recon_kernel<<<NT, 256>>>(0, bdU, out);

    // Join stream B, then downstream tail.
    cudaStreamWaitEvent(0, evJoin, 0);
    accum_cand_kernel<<<NT, 256>>>(beD, ln);
    refine_kernel<<<NT, 256>>>(1, x0, WeU, WeD, beU, ln);
    recon_kernel<<<NT, 256>>>(1, bdD, out + (size_t)NT * DDIM);
}

// round 15
// speedup vs baseline: 1.0955x; 1.0597x over previous
#include <cuda_runtime.h>
#include <cuda_bf16.h>
#include <cstdint>

// Problem constants
#define NT   1024      // tokens = B*S
#define DDIM 768       // activation dim
#define FDIM 8192      // dict size
#define KTOP 64        // topk
#define CAND 96        // refinement candidates (margin 32 over KTOP)
#define CONN 128       // connections per downstream feature
#define NEDGE (FDIM*CONN)
#define BUCKET 256     // fixed per-f_up reverse-edge bucket (mean 128, 11 sigma safe)

// ---------------- device scratch (static globals; no cudaMalloc allowed) ----
__device__ float g_post[(size_t)NT * FDIM];       // upstream pre-topk approx (relu'd)
__device__ float g_dotD[(size_t)NT * FDIM];       // downstream raw dot approx
__device__ float g_xm[NT * DDIM];                 // (x_up - b_dec_up) fp32
__device__ float g_WtU[(size_t)FDIM * DDIM];      // W_dec_up^T   [F,D] fp32
__device__ float g_WtD[(size_t)FDIM * DDIM];      // W_dec_down^T [F,D] fp32
__device__ float g_cup[FDIM];                     // W_enc_down @ b_dec_up
__device__ float g_cdn[FDIM];                     // W_enc_down @ b_dec_down
__device__ int   g_tki_up[NT * KTOP];
__device__ float g_tkv_up[NT * KTOP];
__device__ int   g_tki_dn[NT * KTOP];
__device__ float g_tkv_dn[NT * KTOP];
__device__ int   g_cand_up[NT * CAND];
__device__ int   g_cand_dn[NT * CAND];
__device__ float g_candv_dn[NT * CAND];           // approx values at dn candidates
__device__ float g_eval[NEDGE];                   // masked virtual values (dup->0)
__device__ int   g_pos[FDIM];                     // bucket cursors (== final counts)
__device__ int2  g_rev[(size_t)FDIM * BUCKET];    // packed {f_down, eval bits}

// bf16 operands for tensor-core candidate GEMMs (selection-grade)
__device__ __align__(16) __nv_bfloat16 g_xhi[NT * DDIM];   // (x_up - b_dec_up)
__device__ __align__(16) __nv_bfloat16 g_0hi[NT * DDIM];   // initial_acts
__device__ __align__(16) __nv_bfloat16 g_Uhi[(size_t)FDIM * DDIM];  // W_enc_up
__device__ __align__(16) __nv_bfloat16 g_Dhi[(size_t)FDIM * DDIM];  // W_enc_down

// ======================= low-level helpers ==================================
__device__ __forceinline__ uint32_t s2u(const void* p) {
    uint32_t a;
    asm("{ .reg .u64 t; cvta.to.shared.u64 t, %1; cvt.u32.u64 %0, t; }"
        : "=r"(a) : "l"(p));
    return a;
}
__device__ __forceinline__ void cp16(uint32_t d, const void* s) {
    asm volatile("cp.async.cg.shared.global [%0], [%1], 16;"
                 :: "r"(d), "l"(s) : "memory");
}
#define CP_COMMIT() asm volatile("cp.async.commit_group;" ::: "memory")
#define CP_WAIT(n)  asm volatile("cp.async.wait_group %0;" :: "n"(n) : "memory")

#define LDSM4(r, a) \
    asm volatile("ldmatrix.sync.aligned.m8n8.x4.shared.b16 {%0,%1,%2,%3}, [%4];" \
        : "=r"((r)[0]), "=r"((r)[1]), "=r"((r)[2]), "=r"((r)[3]) : "r"(a))

#define MMA16816(d, a, b0, b1) \
    asm volatile("mma.sync.aligned.m16n8k16.row.col.f32.bf16.bf16.f32 " \
        "{%0,%1,%2,%3},{%4,%5,%6,%7},{%8,%9},{%0,%1,%2,%3};" \
        : "+f"((d)[0]), "+f"((d)[1]), "+f"((d)[2]), "+f"((d)[3]) \
        : "r"((a)[0]), "r"((a)[1]), "r"((a)[2]), "r"((a)[3]), "r"(b0), "r"(b1))

__device__ __forceinline__ unsigned fkey(float f) {
    unsigned u = __float_as_uint(f);
    return (u & 0x80000000u) ? ~u : (u | 0x80000000u);
}

// ---------------- prep / bf16 convert kernels --------------------------------
__global__ void split_xm_kernel(const float* __restrict__ xu,
                                const float* __restrict__ bdU) {
    int i = blockIdx.x * 256 + threadIdx.x;   // float4 index
    if (i >= NT * DDIM / 4) return;
    float4 v = ((const float4*)xu)[i];
    int col = (4 * i) % DDIM;
    v.x -= bdU[col]; v.y -= bdU[col + 1]; v.z -= bdU[col + 2]; v.w -= bdU[col + 3];
    ((float4*)g_xm)[i] = v;
    __nv_bfloat162* H = (__nv_bfloat162*)g_xhi;
    H[2 * i]     = __halves2bfloat162(__float2bfloat16(v.x), __float2bfloat16(v.y));
    H[2 * i + 1] = __halves2bfloat162(__float2bfloat16(v.z), __float2bfloat16(v.w));
}

// which: 0 -> x0 -> g_0hi, 1 -> WeU -> g_Uhi, 2 -> WeD -> g_Dhi (device-resolved)
__global__ void tobf16_kernel(const float* __restrict__ src, int which, int n4) {
    int i = blockIdx.x * 256 + threadIdx.x;
    if (i >= n4) return;
    __nv_bfloat16* hi = which == 0 ? g_0hi : (which == 1 ? g_Uhi : g_Dhi);
    float4 v = ((const float4*)src)[i];
    __nv_bfloat162* H = (__nv_bfloat162*)hi;
    H[2 * i]     = __halves2bfloat162(__float2bfloat16(v.x), __float2bfloat16(v.y));
    H[2 * i + 1] = __halves2bfloat162(__float2bfloat16(v.z), __float2bfloat16(v.w));
}

// ---------------- transpose W_dec [D,F] -> [F,D] ---------------------------
// which=0: WdU -> g_WtU (and zero g_pos for scatter)
// which=1: WdD -> g_WtD
__global__ void transpose_kernel(const float* __restrict__ W, int which) {
    __shared__ float tile[32][33];
    float* Wt = which ? g_WtD : g_WtU;
    int c0 = blockIdx.x * 32, r0 = blockIdx.y * 32;
    int tx = threadIdx.x, ty = threadIdx.y;
    if (which == 0 && blockIdx.y == 0) {
        int idx = blockIdx.x * 256 + ty * 32 + tx;
        if (idx < FDIM) g_pos[idx] = 0;
    }
#pragma unroll
    for (int i = 0; i < 32; i += 8)
        tile[ty + i][tx] = W[(size_t)(r0 + ty + i) * FDIM + c0 + tx];
    __syncthreads();
#pragma unroll
    for (int i = 0; i < 32; i += 8)
        Wt[(size_t)(c0 + ty + i) * DDIM + r0 + tx] = tile[tx][ty + i];
}

// ---------------- c_up/c_dn = W_enc_down @ b_dec_{up,down} -----------------
__global__ __launch_bounds__(256) void biasdot_kernel(
    const float* __restrict__ WeD, const float* __restrict__ bdU,
    const float* __restrict__ bdD) {
    int lane = threadIdx.x & 31, warp = threadIdx.x >> 5;
    int f = blockIdx.x * 8 + warp;
    const float4* w4 = (const float4*)(WeD + (size_t)f * DDIM);
    const float4* u4 = (const float4*)bdU;
    const float4* v4 = (const float4*)bdD;
    float su = 0.f, sd = 0.f;
    for (int q = lane; q < DDIM / 4; q += 32) {
        float4 a = w4[q], u = u4[q], v = v4[q];
        su += a.x * u.x + a.y * u.y + a.z * u.z + a.w * u.w;
        sd += a.x * v.x + a.y * v.y + a.z * v.z + a.w * v.w;
    }
#pragma unroll
    for (int o = 16; o; o >>= 1) {
        su += __shfl_xor_sync(0xffffffffu, su, o);
        sd += __shfl_xor_sync(0xffffffffu, sd, o);
    }
    if (lane == 0) { g_cup[f] = su; g_cdn[f] = sd; }
}

// =================== bf16 mma.sync GEMM: C = A @ B^T (candidate-grade) ======
#define BK 32
#define STAGE_BYTES 16384
#define GEMM_SMEM (3 * STAGE_BYTES)
#define NITER (DDIM / BK)

__global__ __launch_bounds__(256, 1) void gemm_mma(const float* __restrict__ beU) {
    extern __shared__ char smem[];
    const uint32_t sb = s2u(smem);
    const int tid = threadIdx.x;
    const int z = blockIdx.z;
    const int m0 = blockIdx.y << 7, n0 = blockIdx.x << 7;
    const __nv_bfloat16* Ahp = z ? g_0hi : g_xhi;
    const __nv_bfloat16* Bhp = z ? g_Dhi : g_Uhi;
    float* C = z ? g_dotD : g_post;

    const int lane = tid & 31, w = tid >> 5;
    const int wm = w >> 2, wn = w & 3;

    const int rowA = wm * 64 + (lane & 15);
    const int cA = lane >> 4;
    const int sA_ = (rowA >> 1) & 3;
    const int rowB = wn * 32 + ((lane >> 4) << 3) + (lane & 7);
    const int cB = (lane >> 3) & 1;
    const int sB_ = (rowB >> 1) & 3;

    float acc[4][4][4];
#pragma unroll
    for (int a = 0; a < 4; a++)
#pragma unroll
        for (int b = 0; b < 4; b++)
#pragma unroll
            for (int c = 0; c < 4; c++) acc[a][b][c] = 0.f;

    auto load_stage = [&](int it) {
        const int kk = it * BK;
        const uint32_t sbase = sb + (it % 3) * STAGE_BYTES;
#pragma unroll
        for (int i = 0; i < 2; i++) {
            int id = tid + (i << 8);
            int row = id >> 2, c = id & 3;
            const __nv_bfloat16* src = Ahp + (size_t)(m0 + row) * DDIM + kk + (c << 3);
            uint32_t dst = sbase + (row << 6) + ((c ^ ((row >> 1) & 3)) << 4);
            cp16(dst, src);
        }
#pragma unroll
        for (int i = 0; i < 2; i++) {
            int id = tid + (i << 8);
            int row = id >> 2, c = id & 3;
            const __nv_bfloat16* src = Bhp + (size_t)(n0 + row) * DDIM + kk + (c << 3);
            uint32_t dst = sbase + 8192 + (row << 6) + ((c ^ ((row >> 1) & 3)) << 4);
            cp16(dst, src);
        }
        CP_COMMIT();
    };

    load_stage(0);
    load_stage(1);

    for (int it = 0; it < NITER; it++) {
        if (it + 1 < NITER) { CP_WAIT(1); } else { CP_WAIT(0); }
        __syncthreads();

        const uint32_t sbase = sb + (it % 3) * STAGE_BYTES;
#pragma unroll
        for (int ks = 0; ks < 2; ks++) {
            uint32_t ah[4][4], bh[2][4];
            const int ca = ((ks << 1) + cA);
            const int cb = ((ks << 1) + cB);
#pragma unroll
            for (int mi = 0; mi < 4; mi++)
                LDSM4(ah[mi], sbase + ((rowA + (mi << 4)) << 6) + ((ca ^ sA_) << 4));
#pragma unroll
            for (int jb = 0; jb < 2; jb++)
                LDSM4(bh[jb], sbase + 8192 + ((rowB + (jb << 4)) << 6) +
                              ((cb ^ sB_) << 4));
#pragma unroll
            for (int mi = 0; mi < 4; mi++) {
#pragma unroll
                for (int nj = 0; nj < 4; nj++) {
                    const int jb = nj >> 1, o = (nj & 1) << 1;
                    MMA16816(acc[mi][nj], ah[mi], bh[jb][o], bh[jb][o + 1]);
                }
            }
        }
        __syncthreads();
        if (it + 2 < NITER) load_stage(it + 2);
    }

    const int g = lane >> 2, t4 = lane & 3;
#pragma unroll
    for (int mi = 0; mi < 4; mi++) {
#pragma unroll
        for (int nj = 0; nj < 4; nj++) {
            int row = m0 + wm * 64 + (mi << 4) + g;
            int col = n0 + wn * 32 + (nj << 3) + (t4 << 1);
            float v0 = acc[mi][nj][0], v1 = acc[mi][nj][1];
            float v2 = acc[mi][nj][2], v3 = acc[mi][nj][3];
            if (z == 0) {
                float b0 = __ldg(beU + col), b1 = __ldg(beU + col + 1);
                v0 = fmaxf(v0 + b0, 0.f); v1 = fmaxf(v1 + b1, 0.f);
                v2 = fmaxf(v2 + b0, 0.f); v3 = fmaxf(v3 + b1, 0.f);
            }
            *(float2*)(C + (size_t)row * FDIM + col) = make_float2(v0, v1);
            *(float2*)(C + (size_t)(row + 8) * FDIM + col) = make_float2(v2, v3);
        }
    }
}

// ---------------- upstream candidates: register-resident radix select ------
__global__ __launch_bounds__(256) void cand_up_kernel() {
    int n = blockIdx.x, t = threadIdx.x;
    __shared__ int hist[256];
    __shared__ unsigned s_pref;
    __shared__ int s_rem, s_cnt;

    unsigned key[32];
    const float4* p = (const float4*)(g_post + (size_t)n * FDIM);
#pragma unroll
    for (int j = 0; j < 8; j++) {
        float4 x = p[t + 256 * j];
        key[4 * j + 0] = fkey(x.x); key[4 * j + 1] = fkey(x.y);
        key[4 * j + 2] = fkey(x.z); key[4 * j + 3] = fkey(x.w);
    }
    if (t == 0) { s_pref = 0u; s_rem = CAND; s_cnt = 0; }
    __syncthreads();

    unsigned hmask = 0u;
    for (int pass = 0; pass < 4; pass++) {
        int sh = 24 - 8 * pass;
        hist[t] = 0;
        __syncthreads();
        unsigned pref = s_pref;
#pragma unroll
        for (int e = 0; e < 32; e++)
            if ((key[e] & hmask) == pref) atomicAdd(&hist[(key[e] >> sh) & 255], 1);
        __syncthreads();
        if (t == 0) {
            int rem = s_rem, c = 0, b = 255;
            for (; b >= 0; b--) { int h = hist[b]; if (c + h >= rem) break; c += h; }
            s_pref = pref | ((unsigned)b << sh);
            s_rem = rem - c;
        }
        hmask |= (0xFFu << sh);
        __syncthreads();
    }
    unsigned T = s_pref;
#pragma unroll
    for (int e = 0; e < 32; e++) {
        if (key[e] > T) {
            int q = atomicAdd(&s_cnt, 1);
            g_cand_up[n * CAND + q] = 4 * (t + 256 * (e >> 2)) + (e & 3);
        }
    }
    __syncthreads();
#pragma unroll
    for (int e = 0; e < 32; e++) {
        if (key[e] == T) {
            int q = atomicAdd(&s_cnt, 1);
            if (q < CAND) g_cand_up[n * CAND + q] = 4 * (t + 256 * (e >> 2)) + (e & 3);
        }
    }
}

// ---------------- refine: exact fp32 scores for candidates, exact top-K ----
__global__ __launch_bounds__(256) void refine_kernel(
    int which, const float* __restrict__ x0,
    const float* __restrict__ WeU, const float* __restrict__ WeD,
    const float* __restrict__ beU, const float* __restrict__ ln) {
    int n = blockIdx.x, t = threadIdx.x;
    int lane = t & 31, w = t >> 5;
    __shared__ float sx[DDIM];
    __shared__ float sval[128];
    __shared__ int sidx[128];

    const float* xsrc = which ? (x0 + (size_t)n * DDIM) : (g_xm + (size_t)n * DDIM);
    for (int i = t; i < DDIM; i += 256) sx[i] = xsrc[i];
    if (t >= CAND && t < 128) { sval[t] = -1e30f; sidx[t] = 0; }
    __syncthreads();

    const int* cand = which ? g_cand_dn : g_cand_up;
    const float* W = which ? WeD : WeU;
    const float inv = which ? (1.f / ln[n]) : 0.f;
    for (int c = w; c < CAND; c += 8) {
        int f = cand[n * CAND + c];
        const float4* wr = (const float4*)(W + (size_t)f * DDIM);
        const float4* xr = (const float4*)sx;
        float s = 0.f;
#pragma unroll
        for (int q = lane; q < DDIM / 4; q += 32) {
            float4 a = wr[q], b = xr[q];
            s += a.x * b.x + a.y * b.y + a.z * b.z + a.w * b.w;
        }
#pragma unroll
        for (int o = 16; o; o >>= 1) s += __shfl_xor_sync(0xffffffffu, s, o);
        if (lane == 0) {
            float v;
            if (which == 0) {
                v = fmaxf(s + beU[f], 0.f);
            } else {
                v = g_candv_dn[n * CAND + c] +
                    (s - g_dotD[(size_t)n * FDIM + f]) * inv;
            }
            sval[c] = v; sidx[c] = f;
        }
    }
    __syncthreads();

    // bitonic sort 128 descending
    for (int k = 2; k <= 128; k <<= 1) {
        for (int j = k >> 1; j > 0; j >>= 1) {
            if (t < 128) {
                int p = t ^ j;
                if (p > t) {
                    bool up = ((t & k) == 0);
                    float v0 = sval[t], v1 = sval[p];
                    bool sw = up ? (v0 < v1) : (v0 > v1);
                    if (sw) {
                        sval[t] = v1; sval[p] = v0;
                        int tmp = sidx[t]; sidx[t] = sidx[p]; sidx[p] = tmp;
                    }
                }
            }
            __syncthreads();
        }
    }

    if (t < KTOP) {
        if (which) { g_tki_dn[n * KTOP + t] = sidx[t]; g_tkv_dn[n * KTOP + t] = sval[t]; }
        else       { g_tki_up[n * KTOP + t] = sidx[t]; g_tkv_up[n * KTOP + t] = sval[t]; }
    }
}

// ---------------- SDDMM: masked virtual values (fp32 gather) ---------------
__global__ __launch_bounds__(256) void sddmm_kernel(
    const float* __restrict__ WeD, const int* __restrict__ conn) {
    int f = blockIdx.x;
    int t = threadIdx.x, lane = t & 31, warp = t >> 5;
    __shared__ int sconn[CONN];
    __shared__ unsigned bset[FDIM / 32];
    __shared__ unsigned char dup[CONN];
    if (t < CONN) sconn[t] = conn[f * CONN + t];
    bset[t] = 0u;
    __syncthreads();
    if (t < CONN) {
        int j = sconn[t];
        unsigned old = atomicOr(&bset[j >> 5], 1u << (j & 31));
        dup[t] = (unsigned char)((old >> (j & 31)) & 1u);
    }
    __syncthreads();

    const float4* w4 = (const float4*)(WeD + (size_t)f * DDIM);
    float4 a[6];
#pragma unroll
    for (int q = 0; q < 6; q++) a[q] = w4[lane + 32 * q];

    for (int e = warp; e < CONN; e += 8) {
        int j = sconn[e];
        float v = 0.f;
        if (!dup[e]) {
            const float4* b4 = (const float4*)(g_WtU + (size_t)j * DDIM);
#pragma unroll
            for (int q = 0; q < 6; q++) {
                float4 b = b4[lane + 32 * q];
                v += a[q].x * b.x + a[q].y * b.y + a[q].z * b.z + a[q].w * b.w;
            }
#pragma unroll
            for (int o = 16; o; o >>= 1) v += __shfl_xor_sync(0xffffffffu, v, o);
        }
        if (lane == 0) g_eval[f * CONN + e] = v;
    }
}

// ---------------- scatter edges into fixed-slot buckets --------------------
__global__ void scatter_kernel(const int* __restrict__ conn) {
    int e = blockIdx.x * 256 + threadIdx.x;
    int j = conn[e];
    int p = atomicAdd(&g_pos[j], 1);
    g_rev[(size_t)j * BUCKET + p] =
        make_int2(e >> 7, __float_as_int(g_eval[e]));
}

// ---------------- fused: accum + finalize + downstream candidate select ----
__global__ __launch_bounds__(256) void accum_cand_kernel(
    const float* __restrict__ beD, const float* __restrict__ ln) {
    int n = blockIdx.x, t = threadIdx.x;
    __shared__ float srow[FDIM];
    __shared__ int sidx[KTOP];
    __shared__ float sval[KTOP];
    __shared__ int hist[256];
    __shared__ unsigned s_pref;
    __shared__ int s_rem, s_cnt;

    for (int i = t; i < FDIM; i += 256) srow[i] = g_dotD[(size_t)n * FDIM + i];
    if (t < KTOP) { sidx[t] = g_tki_up[n * KTOP + t]; sval[t] = g_tkv_up[n * KTOP + t]; }
    if (t == 0) { s_pref = 0u; s_rem = CAND; s_cnt = 0; }
    __syncthreads();
    for (int k = 0; k < KTOP; k++) {
        float fv = sval[k];
        if (fv == 0.f) continue;
        int j = sidx[k];
        int cnt = g_pos[j];
        const int2* rv = g_rev + (size_t)j * BUCKET;
        for (int q = t; q < cnt; q += 256) {
            int2 r = rv[q];
            atomicAdd(&srow[r.x], fv * __int_as_float(r.y));
        }
    }
    __syncthreads();
    float inv = 1.f / ln[n];
    for (int i = t; i < FDIM; i += 256)
        srow[i] = (srow[i] + g_cup[i]) * inv + beD[i] - g_cdn[i];
    __syncthreads();

    unsigned hmask = 0u;
    for (int pass = 0; pass < 4; pass++) {
        int sh = 24 - 8 * pass;
        hist[t] = 0;
        __syncthreads();
        unsigned pref = s_pref;
        for (int i = t; i < FDIM; i += 256) {
            unsigned key = fkey(srow[i]);
            if ((key & hmask) == pref) atomicAdd(&hist[(key >> sh) & 255], 1);
        }
        __syncthreads();
        if (t == 0) {
            int rem = s_rem, c = 0, b = 255;
            for (; b >= 0; b--) { int h = hist[b]; if (c + h >= rem) break; c += h; }
            s_pref = pref | ((unsigned)b << sh);
            s_rem = rem - c;
        }
        hmask |= (0xFFu << sh);
        __syncthreads();
    }
    unsigned T = s_pref;
    for (int i = t; i < FDIM; i += 256) {
        if (fkey(srow[i]) > T) {
            int q = atomicAdd(&s_cnt, 1);
            g_cand_dn[n * CAND + q] = i;
            g_candv_dn[n * CAND + q] = srow[i];
        }
    }
    __syncthreads();
    for (int i = t; i < FDIM; i += 256) {
        if (fkey(srow[i]) == T) {
            int q = atomicAdd(&s_cnt, 1);
            if (q < CAND) {
                g_cand_dn[n * CAND + q] = i;
                g_candv_dn[n * CAND + q] = srow[i];
            }
        }
    }
}

// ---------------- sparse decode: out = bias + sum topk_v * Wt[idx] ---------
__global__ __launch_bounds__(256) void recon_kernel(
    int which, const float* __restrict__ bias, float* __restrict__ out) {
    int n = blockIdx.x, t = threadIdx.x;
    const float* Wt = which ? g_WtD : g_WtU;
    const int* ti = which ? g_tki_dn : g_tki_up;
    const float* tv = which ? g_tkv_dn : g_tkv_up;
    __shared__ int sidx[KTOP];
    __shared__ float sval[KTOP];
    if (t < KTOP) { sidx[t] = ti[n * KTOP + t]; sval[t] = tv[n * KTOP + t]; }
    __syncthreads();
    float a0 = bias[t], a1 = bias[t + 256], a2 = bias[t + 512];
    for (int k = 0; k < KTOP; k++) {
        const float* w = Wt + (size_t)sidx[k] * DDIM;
        float v = sval[k];
        a0 += v * w[t]; a1 += v * w[t + 256]; a2 += v * w[t + 512];
    }
    float* o = out + (size_t)n * DDIM;
    o[t] = a0; o[t + 256] = a1; o[t + 512] = a2;
}

// ---------------- launch: three-stream fork/join -------------------------------
extern "C" void kernel_launch(void* const* d_in, const int* in_sizes, int n_in,
                              void* d_out, int out_size) {
    (void)in_sizes; (void)n_in; (void)out_size;
    const float* x0  = (const float*)d_in[0];   // initial_acts
    const float* xu  = (const float*)d_in[1];   // x_up
    const float* ln  = (const float*)d_in[2];   // ln_scale [NT]
    const float* WeU = (const float*)d_in[3];   // W_enc_up [F,D]
    const float* beU = (const float*)d_in[4];   // b_enc_up [F]
    const float* WdU = (const float*)d_in[5];   // W_dec_up [D,F]
    const float* bdU = (const float*)d_in[6];   // b_dec_up [D]
    const float* WeD = (const float*)d_in[7];   // W_enc_down [F,D]
    const float* beD = (const float*)d_in[8];   // b_enc_down [F]
    const float* WdD = (const float*)d_in[9];   // W_dec_down [D,F]
    const float* bdD = (const float*)d_in[10];  // b_dec_down [D]
    const int*   conn = (const int*)d_in[11];   // [F,C]
    float* out = (float*)d_out;                 // [2,NT,DDIM]

    static cudaStream_t sB = nullptr, sC = nullptr;
    static cudaEvent_t evFork = nullptr, evT = nullptr, evJoin = nullptr, evC = nullptr;
    if (sB == nullptr) {
        int loPri, hiPri;
        cudaDeviceGetStreamPriorityRange(&loPri, &hiPri);
        cudaStreamCreateWithPriority(&sB, cudaStreamNonBlocking, hiPri);
        cudaStreamCreateWithFlags(&sC, cudaStreamNonBlocking);
        cudaEventCreateWithFlags(&evFork, cudaEventDisableTiming);
        cudaEventCreateWithFlags(&evT, cudaEventDisableTiming);
        cudaEventCreateWithFlags(&evJoin, cudaEventDisableTiming);
        cudaEventCreateWithFlags(&evC, cudaEventDisableTiming);
        cudaFuncSetAttribute(gemm_mma, cudaFuncAttributeMaxDynamicSharedMemorySize,
                             GEMM_SMEM);
    }

    // Fork. Stream B carries ONLY the sddmm dependency chain.
    cudaEventRecord(evFork, 0);
    cudaStreamWaitEvent(sB, evFork, 0);
    cudaStreamWaitEvent(sC, evFork, 0);

    // Stream B: transposeU (zeros g_pos) -> sddmm -> scatter.
    transpose_kernel<<<dim3(FDIM / 32, DDIM / 32), dim3(32, 8), 0, sB>>>(WdU, 0);
    cudaEventRecord(evT, sB);   // g_WtU ready (recon0 on main stream)
    sddmm_kernel<<<FDIM, 256, 0, sB>>>(WeD, conn);
    scatter_kernel<<<NEDGE / 256, 256, 0, sB>>>(conn);
    cudaEventRecord(evJoin, sB);

    // Stream C: off-chain B-side work (consumers are after the join anyway).
    transpose_kernel<<<dim3(FDIM / 32, DDIM / 32), dim3(32, 8), 0, sC>>>(WdD, 1);
    biasdot_kernel<<<FDIM / 8, 256, 0, sC>>>(WeD, bdU, bdD);
    cudaEventRecord(evC, sC);

    // Main stream: upstream spine (identical to R12).
    split_xm_kernel<<<(NT * DDIM / 4 + 255) / 256, 256>>>(xu, bdU);
    tobf16_kernel<<<(NT * DDIM / 4 + 255) / 256, 256>>>(x0, 0, NT * DDIM / 4);
    tobf16_kernel<<<(FDIM * DDIM / 4 + 255) / 256, 256>>>(WeU, 1, FDIM * DDIM / 4);
    tobf16_kernel<<<(FDIM * DDIM / 4 + 255) / 256, 256>>>(WeD, 2, FDIM * DDIM / 4);
    gemm_mma<<<dim3(FDIM / 128, NT / 128, 2), 256, GEMM_SMEM>>>(beU);
    cand_up_kernel<<<NT, 256>>>();
    refine_kernel<<<NT, 256>>>(0, x0, WeU, WeD, beU, ln);
    cudaStreamWaitEvent(0, evT, 0);      // recon0 reads g_WtU
    recon_kernel<<<NT, 256>>>(0, bdU, out);

    // Join B (buckets) and C (cup/cdn, WtD), then downstream tail.
    cudaStreamWaitEvent(0, evJoin, 0);
    cudaStreamWaitEvent(0, evC, 0);
    accum_cand_kernel<<<NT, 256>>>(beD, ln);
    refine_kernel<<<NT, 256>>>(1, x0, WeU, WeD, beU, ln);
    recon_kernel<<<NT, 256>>>(1, bdD, out + (size_t)NT * DDIM);
}

// round 16
// speedup vs baseline: 1.1165x; 1.0191x over previous
#include <cuda_runtime.h>
#include <cuda_bf16.h>
#include <cstdint>

// Problem constants
#define NT   1024      // tokens = B*S
#define DDIM 768       // activation dim
#define FDIM 8192      // dict size
#define KTOP 64        // topk
#define CAND 96        // refinement candidates (margin 32 over KTOP)
#define CONN 128       // connections per downstream feature
#define NEDGE (FDIM*CONN)
#define BUCKET 256     // fixed per-f_up reverse-edge bucket (mean 128, 11 sigma safe)

// ---------------- device scratch (static globals; no cudaMalloc allowed) ----
__device__ float g_post[(size_t)NT * FDIM];       // upstream pre-topk approx (relu'd)
__device__ float g_dotD[(size_t)NT * FDIM];       // downstream raw dot approx
__device__ float g_xm[NT * DDIM];                 // (x_up - b_dec_up) fp32
__device__ float g_WtU[(size_t)FDIM * DDIM];      // W_dec_up^T   [F,D] fp32
__device__ float g_WtD[(size_t)FDIM * DDIM];      // W_dec_down^T [F,D] fp32
__device__ float g_cup[FDIM];                     // W_enc_down @ b_dec_up
__device__ float g_cdn[FDIM];                     // W_enc_down @ b_dec_down
__device__ int   g_tki_up[NT * KTOP];
__device__ float g_tkv_up[NT * KTOP];
__device__ int   g_tki_dn[NT * KTOP];
__device__ float g_tkv_dn[NT * KTOP];
__device__ int   g_cand_up[NT * CAND];
__device__ int   g_cand_dn[NT * CAND];
__device__ float g_candv_dn[NT * CAND];           // approx values at dn candidates
__device__ float g_eval[NEDGE];                   // masked virtual values (dup->0)
__device__ int   g_pos[FDIM];                     // bucket cursors (== final counts)
__device__ int2  g_rev[(size_t)FDIM * BUCKET];    // packed {f_down, eval bits}

// bf16 operands for tensor-core candidate GEMMs (selection-grade)
__device__ __align__(16) __nv_bfloat16 g_xhi[NT * DDIM];   // (x_up - b_dec_up)
__device__ __align__(16) __nv_bfloat16 g_0hi[NT * DDIM];   // initial_acts
__device__ __align__(16) __nv_bfloat16 g_Uhi[(size_t)FDIM * DDIM];  // W_enc_up
__device__ __align__(16) __nv_bfloat16 g_Dhi[(size_t)FDIM * DDIM];  // W_enc_down

// ======================= low-level helpers ==================================
__device__ __forceinline__ uint32_t s2u(const void* p) {
    uint32_t a;
    asm("{ .reg .u64 t; cvta.to.shared.u64 t, %1; cvt.u32.u64 %0, t; }"
        : "=r"(a) : "l"(p));
    return a;
}
__device__ __forceinline__ void cp16(uint32_t d, const void* s) {
    asm volatile("cp.async.cg.shared.global [%0], [%1], 16;"
                 :: "r"(d), "l"(s) : "memory");
}
#define CP_COMMIT() asm volatile("cp.async.commit_group;" ::: "memory")
#define CP_WAIT(n)  asm volatile("cp.async.wait_group %0;" :: "n"(n) : "memory")

#define LDSM4(r, a) \
    asm volatile("ldmatrix.sync.aligned.m8n8.x4.shared.b16 {%0,%1,%2,%3}, [%4];" \
        : "=r"((r)[0]), "=r"((r)[1]), "=r"((r)[2]), "=r"((r)[3]) : "r"(a))

#define MMA16816(d, a, b0, b1) \
    asm volatile("mma.sync.aligned.m16n8k16.row.col.f32.bf16.bf16.f32 " \
        "{%0,%1,%2,%3},{%4,%5,%6,%7},{%8,%9},{%0,%1,%2,%3};" \
        : "+f"((d)[0]), "+f"((d)[1]), "+f"((d)[2]), "+f"((d)[3]) \
        : "r"((a)[0]), "r"((a)[1]), "r"((a)[2]), "r"((a)[3]), "r"(b0), "r"(b1))

__device__ __forceinline__ unsigned fkey(float f) {
    unsigned u = __float_as_uint(f);
    return (u & 0x80000000u) ? ~u : (u | 0x80000000u);
}

// ---------------- prep / bf16 convert kernels --------------------------------
__global__ void split_xm_kernel(const float* __restrict__ xu,
                                const float* __restrict__ bdU) {
    int i = blockIdx.x * 256 + threadIdx.x;   // float4 index
    if (i >= NT * DDIM / 4) return;
    float4 v = ((const float4*)xu)[i];
    int col = (4 * i) % DDIM;
    v.x -= bdU[col]; v.y -= bdU[col + 1]; v.z -= bdU[col + 2]; v.w -= bdU[col + 3];
    ((float4*)g_xm)[i] = v;
    __nv_bfloat162* H = (__nv_bfloat162*)g_xhi;
    H[2 * i]     = __halves2bfloat162(__float2bfloat16(v.x), __float2bfloat16(v.y));
    H[2 * i + 1] = __halves2bfloat162(__float2bfloat16(v.z), __float2bfloat16(v.w));
}

// which: 0 -> x0 -> g_0hi, 1 -> WeU -> g_Uhi, 2 -> WeD -> g_Dhi (device-resolved)
__global__ void tobf16_kernel(const float* __restrict__ src, int which, int n4) {
    int i = blockIdx.x * 256 + threadIdx.x;
    if (i >= n4) return;
    __nv_bfloat16* hi = which == 0 ? g_0hi : (which == 1 ? g_Uhi : g_Dhi);
    float4 v = ((const float4*)src)[i];
    __nv_bfloat162* H = (__nv_bfloat162*)hi;
    H[2 * i]     = __halves2bfloat162(__float2bfloat16(v.x), __float2bfloat16(v.y));
    H[2 * i + 1] = __halves2bfloat162(__float2bfloat16(v.z), __float2bfloat16(v.w));
}

// ---------------- transpose W_dec [D,F] -> [F,D] ---------------------------
// which=0: WdU -> g_WtU (and zero g_pos for scatter)
// which=1: WdD -> g_WtD
__global__ void transpose_kernel(const float* __restrict__ W, int which) {
    __shared__ float tile[32][33];
    float* Wt = which ? g_WtD : g_WtU;
    int c0 = blockIdx.x * 32, r0 = blockIdx.y * 32;
    int tx = threadIdx.x, ty = threadIdx.y;
    if (which == 0 && blockIdx.y == 0) {
        int idx = blockIdx.x * 256 + ty * 32 + tx;
        if (idx < FDIM) g_pos[idx] = 0;
    }
#pragma unroll
    for (int i = 0; i < 32; i += 8)
        tile[ty + i][tx] = W[(size_t)(r0 + ty + i) * FDIM + c0 + tx];
    __syncthreads();
#pragma unroll
    for (int i = 0; i < 32; i += 8)
        Wt[(size_t)(c0 + ty + i) * DDIM + r0 + tx] = tile[tx][ty + i];
}

// ---------------- c_up/c_dn = W_enc_down @ b_dec_{up,down} -----------------
__global__ __launch_bounds__(256) void biasdot_kernel(
    const float* __restrict__ WeD, const float* __restrict__ bdU,
    const float* __restrict__ bdD) {
    int lane = threadIdx.x & 31, warp = threadIdx.x >> 5;
    int f = blockIdx.x * 8 + warp;
    const float4* w4 = (const float4*)(WeD + (size_t)f * DDIM);
    const float4* u4 = (const float4*)bdU;
    const float4* v4 = (const float4*)bdD;
    float su = 0.f, sd = 0.f;
    for (int q = lane; q < DDIM / 4; q += 32) {
        float4 a = w4[q], u = u4[q], v = v4[q];
        su += a.x * u.x + a.y * u.y + a.z * u.z + a.w * u.w;
        sd += a.x * v.x + a.y * v.y + a.z * v.z + a.w * v.w;
    }
#pragma unroll
    for (int o = 16; o; o >>= 1) {
        su += __shfl_xor_sync(0xffffffffu, su, o);
        sd += __shfl_xor_sync(0xffffffffu, sd, o);
    }
    if (lane == 0) { g_cup[f] = su; g_cdn[f] = sd; }
}

// =================== bf16 mma.sync GEMM: C = A @ B^T (candidate-grade) ======
// z passed as kernel arg so the two GEMMs can be launched/overlapped separately.
#define BK 32
#define STAGE_BYTES 16384
#define GEMM_SMEM (3 * STAGE_BYTES)
#define NITER (DDIM / BK)

__global__ __launch_bounds__(256, 1) void gemm_mma(const float* __restrict__ beU,
                                                   int z) {
    extern __shared__ char smem[];
    const uint32_t sb = s2u(smem);
    const int tid = threadIdx.x;
    const int m0 = blockIdx.y << 7, n0 = blockIdx.x << 7;
    const __nv_bfloat16* Ahp = z ? g_0hi : g_xhi;
    const __nv_bfloat16* Bhp = z ? g_Dhi : g_Uhi;
    float* C = z ? g_dotD : g_post;

    const int lane = tid & 31, w = tid >> 5;
    const int wm = w >> 2, wn = w & 3;

    const int rowA = wm * 64 + (lane & 15);
    const int cA = lane >> 4;
    const int sA_ = (rowA >> 1) & 3;
    const int rowB = wn * 32 + ((lane >> 4) << 3) + (lane & 7);
    const int cB = (lane >> 3) & 1;
    const int sB_ = (rowB >> 1) & 3;

    float acc[4][4][4];
#pragma unroll
    for (int a = 0; a < 4; a++)
#pragma unroll
        for (int b = 0; b < 4; b++)
#pragma unroll
            for (int c = 0; c < 4; c++) acc[a][b][c] = 0.f;

    auto load_stage = [&](int it) {
        const int kk = it * BK;
        const uint32_t sbase = sb + (it % 3) * STAGE_BYTES;
#pragma unroll
        for (int i = 0; i < 2; i++) {
            int id = tid + (i << 8);
            int row = id >> 2, c = id & 3;
            const __nv_bfloat16* src = Ahp + (size_t)(m0 + row) * DDIM + kk + (c << 3);
            uint32_t dst = sbase + (row << 6) + ((c ^ ((row >> 1) & 3)) << 4);
            cp16(dst, src);
        }
#pragma unroll
        for (int i = 0; i < 2; i++) {
            int id = tid + (i << 8);
            int row = id >> 2, c = id & 3;
            const __nv_bfloat16* src = Bhp + (size_t)(n0 + row) * DDIM + kk + (c << 3);
            uint32_t dst = sbase + 8192 + (row << 6) + ((c ^ ((row >> 1) & 3)) << 4);
            cp16(dst, src);
        }
        CP_COMMIT();
    };

    load_stage(0);
    load_stage(1);

    for (int it = 0; it < NITER; it++) {
        if (it + 1 < NITER) { CP_WAIT(1); } else { CP_WAIT(0); }
        __syncthreads();

        const uint32_t sbase = sb + (it % 3) * STAGE_BYTES;
#pragma unroll
        for (int ks = 0; ks < 2; ks++) {
            uint32_t ah[4][4], bh[2][4];
            const int ca = ((ks << 1) + cA);
            const int cb = ((ks << 1) + cB);
#pragma unroll
            for (int mi = 0; mi < 4; mi++)
                LDSM4(ah[mi], sbase + ((rowA + (mi << 4)) << 6) + ((ca ^ sA_) << 4));
#pragma unroll
            for (int jb = 0; jb < 2; jb++)
                LDSM4(bh[jb], sbase + 8192 + ((rowB + (jb << 4)) << 6) +
                              ((cb ^ sB_) << 4));
#pragma unroll
            for (int mi = 0; mi < 4; mi++) {
#pragma unroll
                for (int nj = 0; nj < 4; nj++) {
                    const int jb = nj >> 1, o = (nj & 1) << 1;
                    MMA16816(acc[mi][nj], ah[mi], bh[jb][o], bh[jb][o + 1]);
                }
            }
        }
        __syncthreads();
        if (it + 2 < NITER) load_stage(it + 2);
    }

    const int g = lane >> 2, t4 = lane & 3;
#pragma unroll
    for (int mi = 0; mi < 4; mi++) {
#pragma unroll
        for (int nj = 0; nj < 4; nj++) {
            int row = m0 + wm * 64 + (mi << 4) + g;
            int col = n0 + wn * 32 + (nj << 3) + (t4 << 1);
            float v0 = acc[mi][nj][0], v1 = acc[mi][nj][1];
            float v2 = acc[mi][nj][2], v3 = acc[mi][nj][3];
            if (z == 0) {
                float b0 = __ldg(beU + col), b1 = __ldg(beU + col + 1);
                v0 = fmaxf(v0 + b0, 0.f); v1 = fmaxf(v1 + b1, 0.f);
                v2 = fmaxf(v2 + b0, 0.f); v3 = fmaxf(v3 + b1, 0.f);
            }
            *(float2*)(C + (size_t)row * FDIM + col) = make_float2(v0, v1);
            *(float2*)(C + (size_t)(row + 8) * FDIM + col) = make_float2(v2, v3);
        }
    }
}

// ---------------- upstream candidates: register-resident radix select ------
__global__ __launch_bounds__(256) void cand_up_kernel() {
    int n = blockIdx.x, t = threadIdx.x;
    __shared__ int hist[256];
    __shared__ unsigned s_pref;
    __shared__ int s_rem, s_cnt;

    unsigned key[32];
    const float4* p = (const float4*)(g_post + (size_t)n * FDIM);
#pragma unroll
    for (int j = 0; j < 8; j++) {
        float4 x = p[t + 256 * j];
        key[4 * j + 0] = fkey(x.x); key[4 * j + 1] = fkey(x.y);
        key[4 * j + 2] = fkey(x.z); key[4 * j + 3] = fkey(x.w);
    }
    if (t == 0) { s_pref = 0u; s_rem = CAND; s_cnt = 0; }
    __syncthreads();

    unsigned hmask = 0u;
    for (int pass = 0; pass < 4; pass++) {
        int sh = 24 - 8 * pass;
        hist[t] = 0;
        __syncthreads();
        unsigned pref = s_pref;
#pragma unroll
        for (int e = 0; e < 32; e++)
            if ((key[e] & hmask) == pref) atomicAdd(&hist[(key[e] >> sh) & 255], 1);
        __syncthreads();
        if (t == 0) {
            int rem = s_rem, c = 0, b = 255;
            for (; b >= 0; b--) { int h = hist[b]; if (c + h >= rem) break; c += h; }
            s_pref = pref | ((unsigned)b << sh);
            s_rem = rem - c;
        }
        hmask |= (0xFFu << sh);
        __syncthreads();
    }
    unsigned T = s_pref;
#pragma unroll
    for (int e = 0; e < 32; e++) {
        if (key[e] > T) {
            int q = atomicAdd(&s_cnt, 1);
            g_cand_up[n * CAND + q] = 4 * (t + 256 * (e >> 2)) + (e & 3);
        }
    }
    __syncthreads();
#pragma unroll
    for (int e = 0; e < 32; e++) {
        if (key[e] == T) {
            int q = atomicAdd(&s_cnt, 1);
            if (q < CAND) g_cand_up[n * CAND + q] = 4 * (t + 256 * (e >> 2)) + (e & 3);
        }
    }
}

// ---------------- refine: exact fp32 scores for candidates, exact top-K ----
__global__ __launch_bounds__(256) void refine_kernel(
    int which, const float* __restrict__ x0,
    const float* __restrict__ WeU, const float* __restrict__ WeD,
    const float* __restrict__ beU, const float* __restrict__ ln) {
    int n = blockIdx.x, t = threadIdx.x;
    int lane = t & 31, w = t >> 5;
    __shared__ float sx[DDIM];
    __shared__ float sval[128];
    __shared__ int sidx[128];

    const float* xsrc = which ? (x0 + (size_t)n * DDIM) : (g_xm + (size_t)n * DDIM);
    for (int i = t; i < DDIM; i += 256) sx[i] = xsrc[i];
    if (t >= CAND && t < 128) { sval[t] = -1e30f; sidx[t] = 0; }
    __syncthreads();

    const int* cand = which ? g_cand_dn : g_cand_up;
    const float* W = which ? WeD : WeU;
    const float inv = which ? (1.f / ln[n]) : 0.f;
    for (int c = w; c < CAND; c += 8) {
        int f = cand[n * CAND + c];
        const float4* wr = (const float4*)(W + (size_t)f * DDIM);
        const float4* xr = (const float4*)sx;
        float s = 0.f;
#pragma unroll
        for (int q = lane; q < DDIM / 4; q += 32) {
            float4 a = wr[q], b = xr[q];
            s += a.x * b.x + a.y * b.y + a.z * b.z + a.w * b.w;
        }
#pragma unroll
        for (int o = 16; o; o >>= 1) s += __shfl_xor_sync(0xffffffffu, s, o);
        if (lane == 0) {
            float v;
            if (which == 0) {
                v = fmaxf(s + beU[f], 0.f);
            } else {
                v = g_candv_dn[n * CAND + c] +
                    (s - g_dotD[(size_t)n * FDIM + f]) * inv;
            }
            sval[c] = v; sidx[c] = f;
        }
    }
    __syncthreads();

    // bitonic sort 128 descending
    for (int k = 2; k <= 128; k <<= 1) {
        for (int j = k >> 1; j > 0; j >>= 1) {
            if (t < 128) {
                int p = t ^ j;
                if (p > t) {
                    bool up = ((t & k) == 0);
                    float v0 = sval[t], v1 = sval[p];
                    bool sw = up ? (v0 < v1) : (v0 > v1);
                    if (sw) {
                        sval[t] = v1; sval[p] = v0;
                        int tmp = sidx[t]; sidx[t] = sidx[p]; sidx[p] = tmp;
                    }
                }
            }
            __syncthreads();
        }
    }

    if (t < KTOP) {
        if (which) { g_tki_dn[n * KTOP + t] = sidx[t]; g_tkv_dn[n * KTOP + t] = sval[t]; }
        else       { g_tki_up[n * KTOP + t] = sidx[t]; g_tkv_up[n * KTOP + t] = sval[t]; }
    }
}

// ---------------- SDDMM: masked virtual values (fp32 gather) ---------------
__global__ __launch_bounds__(256) void sddmm_kernel(
    const float* __restrict__ WeD, const int* __restrict__ conn) {
    int f = blockIdx.x;
    int t = threadIdx.x, lane = t & 31, warp = t >> 5;
    __shared__ int sconn[CONN];
    __shared__ unsigned bset[FDIM / 32];
    __shared__ unsigned char dup[CONN];
    if (t < CONN) sconn[t] = conn[f * CONN + t];
    bset[t] = 0u;
    __syncthreads();
    if (t < CONN) {
        int j = sconn[t];
        unsigned old = atomicOr(&bset[j >> 5], 1u << (j & 31));
        dup[t] = (unsigned char)((old >> (j & 31)) & 1u);
    }
    __syncthreads();

    const float4* w4 = (const float4*)(WeD + (size_t)f * DDIM);
    float4 a[6];
#pragma unroll
    for (int q = 0; q < 6; q++) a[q] = w4[lane + 32 * q];

    for (int e = warp; e < CONN; e += 8) {
        int j = sconn[e];
        float v = 0.f;
        if (!dup[e]) {
            const float4* b4 = (const float4*)(g_WtU + (size_t)j * DDIM);
#pragma unroll
            for (int q = 0; q < 6; q++) {
                float4 b = b4[lane + 32 * q];
                v += a[q].x * b.x + a[q].y * b.y + a[q].z * b.z + a[q].w * b.w;
            }
#pragma unroll
            for (int o = 16; o; o >>= 1) v += __shfl_xor_sync(0xffffffffu, v, o);
        }
        if (lane == 0) g_eval[f * CONN + e] = v;
    }
}

// ---------------- scatter edges into fixed-slot buckets --------------------
__global__ void scatter_kernel(const int* __restrict__ conn) {
    int e = blockIdx.x * 256 + threadIdx.x;
    int j = conn[e];
    int p = atomicAdd(&g_pos[j], 1);
    g_rev[(size_t)j * BUCKET + p] =
        make_int2(e >> 7, __float_as_int(g_eval[e]));
}

// ---------------- fused: accum + finalize + downstream candidate select ----
__global__ __launch_bounds__(256) void accum_cand_kernel(
    const float* __restrict__ beD, const float* __restrict__ ln) {
    int n = blockIdx.x, t = threadIdx.x;
    __shared__ float srow[FDIM];
    __shared__ int sidx[KTOP];
    __shared__ float sval[KTOP];
    __shared__ int hist[256];
    __shared__ unsigned s_pref;
    __shared__ int s_rem, s_cnt;

    for (int i = t; i < FDIM; i += 256) srow[i] = g_dotD[(size_t)n * FDIM + i];
    if (t < KTOP) { sidx[t] = g_tki_up[n * KTOP + t]; sval[t] = g_tkv_up[n * KTOP + t]; }
    if (t == 0) { s_pref = 0u; s_rem = CAND; s_cnt = 0; }
    __syncthreads();
    for (int k = 0; k < KTOP; k++) {
        float fv = sval[k];
        if (fv == 0.f) continue;
        int j = sidx[k];
        int cnt = g_pos[j];
        const int2* rv = g_rev + (size_t)j * BUCKET;
        for (int q = t; q < cnt; q += 256) {
            int2 r = rv[q];
            atomicAdd(&srow[r.x], fv * __int_as_float(r.y));
        }
    }
    __syncthreads();
    float inv = 1.f / ln[n];
    for (int i = t; i < FDIM; i += 256)
        srow[i] = (srow[i] + g_cup[i]) * inv + beD[i] - g_cdn[i];
    __syncthreads();

    unsigned hmask = 0u;
    for (int pass = 0; pass < 4; pass++) {
        int sh = 24 - 8 * pass;
        hist[t] = 0;
        __syncthreads();
        unsigned pref = s_pref;
        for (int i = t; i < FDIM; i += 256) {
            unsigned key = fkey(srow[i]);
            if ((key & hmask) == pref) atomicAdd(&hist[(key >> sh) & 255], 1);
        }
        __syncthreads();
        if (t == 0) {
            int rem = s_rem, c = 0, b = 255;
            for (; b >= 0; b--) { int h = hist[b]; if (c + h >= rem) break; c += h; }
            s_pref = pref | ((unsigned)b << sh);
            s_rem = rem - c;
        }
        hmask |= (0xFFu << sh);
        __syncthreads();
    }
    unsigned T = s_pref;
    for (int i = t; i < FDIM; i += 256) {
        if (fkey(srow[i]) > T) {
            int q = atomicAdd(&s_cnt, 1);
            g_cand_dn[n * CAND + q] = i;
            g_candv_dn[n * CAND + q] = srow[i];
        }
    }
    __syncthreads();
    for (int i = t; i < FDIM; i += 256) {
        if (fkey(srow[i]) == T) {
            int q = atomicAdd(&s_cnt, 1);
            if (q < CAND) {
                g_cand_dn[n * CAND + q] = i;
                g_candv_dn[n * CAND + q] = srow[i];
            }
        }
    }
}

// ---------------- sparse decode: out = bias + sum topk_v * Wt[idx] ---------
__global__ __launch_bounds__(256) void recon_kernel(
    int which, const float* __restrict__ bias, float* __restrict__ out) {
    int n = blockIdx.x, t = threadIdx.x;
    const float* Wt = which ? g_WtD : g_WtU;
    const int* ti = which ? g_tki_dn : g_tki_up;
    const float* tv = which ? g_tkv_dn : g_tkv_up;
    __shared__ int sidx[KTOP];
    __shared__ float sval[KTOP];
    if (t < KTOP) { sidx[t] = ti[n * KTOP + t]; sval[t] = tv[n * KTOP + t]; }
    __syncthreads();
    float a0 = bias[t], a1 = bias[t + 256], a2 = bias[t + 512];
    for (int k = 0; k < KTOP; k++) {
        const float* w = Wt + (size_t)sidx[k] * DDIM;
        float v = sval[k];
        a0 += v * w[t]; a1 += v * w[t + 256]; a2 += v * w[t + 512];
    }
    float* o = out + (size_t)n * DDIM;
    o[t] = a0; o[t + 256] = a1; o[t + 512] = a2;
}

// ---------------- launch: four-stream fork/join --------------------------------
extern "C" void kernel_launch(void* const* d_in, const int* in_sizes, int n_in,
                              void* d_out, int out_size) {
    (void)in_sizes; (void)n_in; (void)out_size;
    const float* x0  = (const float*)d_in[0];   // initial_acts
    const float* xu  = (const float*)d_in[1];   // x_up
    const float* ln  = (const float*)d_in[2];   // ln_scale [NT]
    const float* WeU = (const float*)d_in[3];   // W_enc_up [F,D]
    const float* beU = (const float*)d_in[4];   // b_enc_up [F]
    const float* WdU = (const float*)d_in[5];   // W_dec_up [D,F]
    const float* bdU = (const float*)d_in[6];   // b_dec_up [D]
    const float* WeD = (const float*)d_in[7];   // W_enc_down [F,D]
    const float* beD = (const float*)d_in[8];   // b_enc_down [F]
    const float* WdD = (const float*)d_in[9];   // W_dec_down [D,F]
    const float* bdD = (const float*)d_in[10];  // b_dec_down [D]
    const int*   conn = (const int*)d_in[11];   // [F,C]
    float* out = (float*)d_out;                 // [2,NT,DDIM]

    static cudaStream_t sB = nullptr, sC = nullptr, sD = nullptr;
    static cudaEvent_t evFork = nullptr, evT = nullptr, evJoin = nullptr,
                       evC = nullptr, evG0 = nullptr, evG1 = nullptr;
    if (sB == nullptr) {
        int loPri, hiPri;
        cudaDeviceGetStreamPriorityRange(&loPri, &hiPri);
        cudaStreamCreateWithPriority(&sB, cudaStreamNonBlocking, hiPri);
        cudaStreamCreateWithFlags(&sC, cudaStreamNonBlocking);
        cudaStreamCreateWithFlags(&sD, cudaStreamNonBlocking);
        cudaEventCreateWithFlags(&evFork, cudaEventDisableTiming);
        cudaEventCreateWithFlags(&evT, cudaEventDisableTiming);
        cudaEventCreateWithFlags(&evJoin, cudaEventDisableTiming);
        cudaEventCreateWithFlags(&evC, cudaEventDisableTiming);
        cudaEventCreateWithFlags(&evG0, cudaEventDisableTiming);
        cudaEventCreateWithFlags(&evG1, cudaEventDisableTiming);
        cudaFuncSetAttribute(gemm_mma, cudaFuncAttributeMaxDynamicSharedMemorySize,
                             GEMM_SMEM);
    }

    // Fork.
    cudaEventRecord(evFork, 0);
    cudaStreamWaitEvent(sB, evFork, 0);
    cudaStreamWaitEvent(sC, evFork, 0);

    // Stream B: transposeU (zeros g_pos) -> sddmm -> scatter.
    transpose_kernel<<<dim3(FDIM / 32, DDIM / 32), dim3(32, 8), 0, sB>>>(WdU, 0);
    cudaEventRecord(evT, sB);   // g_WtU ready (recon0 on main stream)
    sddmm_kernel<<<FDIM, 256, 0, sB>>>(WeD, conn);
    scatter_kernel<<<NEDGE / 256, 256, 0, sB>>>(conn);
    cudaEventRecord(evJoin, sB);

    // Stream C: off-chain side work (tobf16(WeD) feeds gemm1; rest feeds tail).
    tobf16_kernel<<<(FDIM * DDIM / 4 + 255) / 256, 256, 0, sC>>>(WeD, 2, FDIM * DDIM / 4);
    tobf16_kernel<<<(NT * DDIM / 4 + 255) / 256, 256, 0, sC>>>(x0, 0, NT * DDIM / 4);
    transpose_kernel<<<dim3(FDIM / 32, DDIM / 32), dim3(32, 8), 0, sC>>>(WdD, 1);
    biasdot_kernel<<<FDIM / 8, 256, 0, sC>>>(WeD, bdU, bdD);
    cudaEventRecord(evC, sC);

    // Main stream: gemm0 path only.
    split_xm_kernel<<<(NT * DDIM / 4 + 255) / 256, 256>>>(xu, bdU);
    tobf16_kernel<<<(FDIM * DDIM / 4 + 255) / 256, 256>>>(WeU, 1, FDIM * DDIM / 4);
    gemm_mma<<<dim3(FDIM / 128, NT / 128), 256, GEMM_SMEM>>>(beU, 0);
    cudaEventRecord(evG0, 0);

    // Stream D: gemm1 starts after gemm0 (full-width each) + its inputs (evC).
    cudaStreamWaitEvent(sD, evG0, 0);
    cudaStreamWaitEvent(sD, evC, 0);
    gemm_mma<<<dim3(FDIM / 128, NT / 128), 256, GEMM_SMEM, sD>>>(beU, 1);
    cudaEventRecord(evG1, sD);

    // Main stream: selection chain overlaps gemm1.
    cand_up_kernel<<<NT, 256>>>();
    refine_kernel<<<NT, 256>>>(0, x0, WeU, WeD, beU, ln);
    cudaStreamWaitEvent(0, evT, 0);      // recon0 reads g_WtU
    recon_kernel<<<NT, 256>>>(0, bdU, out);

    // Join B (buckets), C (cup/cdn, WtD), D (dotD), then downstream tail.
    cudaStreamWaitEvent(0, evJoin, 0);
    cudaStreamWaitEvent(0, evC, 0);
    cudaStreamWaitEvent(0, evG1, 0);
    accum_cand_kernel<<<NT, 256>>>(beD, ln);
    refine_kernel<<<NT, 256>>>(1, x0, WeU, WeD, beU, ln);
    recon_kernel<<<NT, 256>>>(1, bdD, out + (size_t)NT * DDIM);
}